// round 1
// baseline (speedup 1.0000x reference)
#include <cuda_runtime.h>
#include <cuda_bf16.h>
#include <math.h>

// Problem shape (fixed by reference):
//   hidden_states [4, 2048, 1024] f32, W_qkv [1024, 3072] f32 -> out [4, 2048, 1024] f32
#define BATCH   4
#define SEQ     2048
#define EMBED   1024
#define THREE_E 3072

// Scratch (device globals; allocation in kernel_launch is forbidden)
__device__ float g_qkv[(long)BATCH * SEQ * THREE_E];      // [B*S, 3E]  96 MB
__device__ float g_scores[(long)BATCH * SEQ * SEQ];       // [B, S, S]  64 MB

// ---------------------------------------------------------------------------
// Register-tiled SGEMM, 128x128 block tile, BK=8, 8x8 per-thread microtile.
// TRANSB=false : C[m,n] = alpha * sum_k A[m,k] * B[k,n]   (B is [K,N], ldb)
// TRANSB=true  : C[m,n] = alpha * sum_k A[m,k] * B[n,k]   (B is [N,K], ldb)
// All dims assumed multiples of tile sizes (true for this problem).
// ---------------------------------------------------------------------------
#define BM 128
#define BN 128
#define BK 8
#define TM 8
#define TN 8
// threads = (BM/TM)*(BN/TN) = 256

template <bool TRANSB>
__global__ __launch_bounds__(256)
void sgemm_kernel(const float* __restrict__ A, const float* __restrict__ B,
                  float* __restrict__ C,
                  int M, int N, int K, int lda, int ldb, int ldc,
                  long long strideA, long long strideB, long long strideC,
                  float alpha)
{
    const int bz = blockIdx.z;
    A += (long long)bz * strideA;
    B += (long long)bz * strideB;
    C += (long long)bz * strideC;

    __shared__ float As[BK][BM];
    __shared__ float Bs[BK][BN];

    const int tid = threadIdx.x;
    const int tx = tid % 16;           // -> N direction
    const int ty = tid / 16;           // -> M direction

    // A-tile load indices: 128 rows x 8 cols = 256 float4 (one per thread)
    const int aRow  = tid >> 1;        // 0..127
    const int aCol4 = (tid & 1) * 4;   // 0 or 4
    // B-tile (NN) load indices: 8 rows x 128 cols = 256 float4
    const int bRow  = tid >> 5;        // 0..7
    const int bCol4 = (tid & 31) * 4;  // 0..124

    float acc[TM][TN];
#pragma unroll
    for (int i = 0; i < TM; i++)
#pragma unroll
        for (int j = 0; j < TN; j++) acc[i][j] = 0.0f;

    const int blockRow = blockIdx.y * BM;
    const int blockCol = blockIdx.x * BN;

    for (int k0 = 0; k0 < K; k0 += BK) {
        // ---- load A tile (transposed into As[k][m]) ----
        {
            const float4 av = *reinterpret_cast<const float4*>(
                &A[(long long)(blockRow + aRow) * lda + k0 + aCol4]);
            As[aCol4 + 0][aRow] = av.x;
            As[aCol4 + 1][aRow] = av.y;
            As[aCol4 + 2][aRow] = av.z;
            As[aCol4 + 3][aRow] = av.w;
        }
        // ---- load B tile ----
        if (!TRANSB) {
            const float4 bv = *reinterpret_cast<const float4*>(
                &B[(long long)(k0 + bRow) * ldb + blockCol + bCol4]);
            *reinterpret_cast<float4*>(&Bs[bRow][bCol4]) = bv;
        } else {
            // B is [N, K] row-major; tile is 128 n-rows x 8 k-cols, same shape as A
            const float4 bv = *reinterpret_cast<const float4*>(
                &B[(long long)(blockCol + aRow) * ldb + k0 + aCol4]);
            Bs[aCol4 + 0][aRow] = bv.x;
            Bs[aCol4 + 1][aRow] = bv.y;
            Bs[aCol4 + 2][aRow] = bv.z;
            Bs[aCol4 + 3][aRow] = bv.w;
        }
        __syncthreads();

#pragma unroll
        for (int k = 0; k < BK; k++) {
            float ar[TM], br[TN];
#pragma unroll
            for (int i = 0; i < TM; i++) ar[i] = As[k][ty * TM + i];
#pragma unroll
            for (int j = 0; j < TN; j++) br[j] = Bs[k][tx * TN + j];
#pragma unroll
            for (int i = 0; i < TM; i++)
#pragma unroll
                for (int j = 0; j < TN; j++)
                    acc[i][j] = fmaf(ar[i], br[j], acc[i][j]);
        }
        __syncthreads();
    }

    const int rowC = blockRow + ty * TM;
    const int colC = blockCol + tx * TN;
#pragma unroll
    for (int i = 0; i < TM; i++) {
#pragma unroll
        for (int j = 0; j < TN; j += 4) {
            float4 v;
            v.x = acc[i][j + 0] * alpha;
            v.y = acc[i][j + 1] * alpha;
            v.z = acc[i][j + 2] * alpha;
            v.w = acc[i][j + 3] * alpha;
            *reinterpret_cast<float4*>(&C[(long long)(rowC + i) * ldc + colC + j]) = v;
        }
    }
}

// ---------------------------------------------------------------------------
// Row softmax over rows of length SEQ (2048). One block (256 threads) per row.
// ---------------------------------------------------------------------------
__global__ __launch_bounds__(256)
void softmax_rows_kernel(float* __restrict__ S)
{
    const long long row = blockIdx.x;
    float* p = S + row * (long long)SEQ;
    const int tid = threadIdx.x;

    __shared__ float red[256];

    float vals[SEQ / 256];
    float m = -INFINITY;
#pragma unroll
    for (int i = 0; i < SEQ / 256; i++) {
        vals[i] = p[tid + i * 256];
        m = fmaxf(m, vals[i]);
    }
    red[tid] = m;
    __syncthreads();
    for (int s = 128; s > 0; s >>= 1) {
        if (tid < s) red[tid] = fmaxf(red[tid], red[tid + s]);
        __syncthreads();
    }
    m = red[0];
    __syncthreads();

    float sum = 0.0f;
#pragma unroll
    for (int i = 0; i < SEQ / 256; i++) {
        vals[i] = expf(vals[i] - m);
        sum += vals[i];
    }
    red[tid] = sum;
    __syncthreads();
    for (int s = 128; s > 0; s >>= 1) {
        if (tid < s) red[tid] += red[tid + s];
        __syncthreads();
    }
    const float inv = 1.0f / red[0];

#pragma unroll
    for (int i = 0; i < SEQ / 256; i++) {
        p[tid + i * 256] = vals[i] * inv;
    }
}

// ---------------------------------------------------------------------------
extern "C" void kernel_launch(void* const* d_in, const int* in_sizes, int n_in,
                              void* d_out, int out_size)
{
    const float* X = (const float*)d_in[0];   // [B*S, E]
    const float* W = (const float*)d_in[1];   // [E, 3E]
    float* out = (float*)d_out;               // [B*S, E]

    float* qkv = nullptr;
    float* scores = nullptr;
    cudaGetSymbolAddress((void**)&qkv, g_qkv);
    cudaGetSymbolAddress((void**)&scores, g_scores);

    const float scale = 1.0f / 32.0f;  // 1/sqrt(1024)

    // 1) QKV = X @ W      M=8192, N=3072, K=1024
    {
        dim3 grid(THREE_E / BN, (BATCH * SEQ) / BM, 1);
        sgemm_kernel<false><<<grid, 256>>>(
            X, W, qkv,
            BATCH * SEQ, THREE_E, EMBED,
            EMBED, THREE_E, THREE_E,
            0LL, 0LL, 0LL, 1.0f);
    }

    // 2) scores[b] = scale * Q[b] @ K[b]^T     M=N=2048, K=1024, batched over z
    {
        dim3 grid(SEQ / BN, SEQ / BM, BATCH);
        const float* Q = qkv;                 // cols [0, E)
        const float* Km = qkv + EMBED;        // cols [E, 2E)
        sgemm_kernel<true><<<grid, 256>>>(
            Q, Km, scores,
            SEQ, SEQ, EMBED,
            THREE_E, THREE_E, SEQ,
            (long long)SEQ * THREE_E, (long long)SEQ * THREE_E,
            (long long)SEQ * SEQ, scale);
    }

    // 3) softmax over rows of scores
    {
        softmax_rows_kernel<<<BATCH * SEQ, 256>>>(scores);
    }

    // 4) out[b] = P[b] @ V[b]     M=2048, N=1024, K=2048, batched
    {
        dim3 grid(EMBED / BN, SEQ / BM, BATCH);
        const float* V = qkv + 2 * EMBED;     // cols [2E, 3E)
        sgemm_kernel<false><<<grid, 256>>>(
            scores, V, out,
            SEQ, EMBED, SEQ,
            SEQ, THREE_E, EMBED,
            (long long)SEQ * SEQ, (long long)SEQ * THREE_E,
            (long long)SEQ * EMBED, 1.0f);
    }
}

// round 3
// speedup vs baseline: 1.6731x; 1.6731x over previous
#include <cuda_runtime.h>
#include <cuda_bf16.h>
#include <cstdint>
#include <math.h>

// Problem shape (fixed by reference):
//   hidden_states [4, 2048, 1024] f32, W_qkv [1024, 3072] f32 -> out [4, 2048, 1024] f32
#define BATCH   4
#define SEQ     2048
#define EMBED   1024
#define THREE_E 3072

// Scratch (device globals; allocation in kernel_launch is forbidden)
__device__ float g_qkv[(size_t)BATCH * SEQ * THREE_E];      // [B*S, 3E]  96 MB
__device__ float g_scores[(size_t)BATCH * SEQ * SEQ];       // [B, S, S]  64 MB

// ============================================================================
// helpers
// ============================================================================
__device__ __forceinline__ uint32_t smem_to_u32(const void* smem_ptr) {
    uint32_t addr;
    asm("{ .reg .u64 tmp; cvta.to.shared.u64 tmp, %1; cvt.u32.u64 %0, tmp; }"
        : "=r"(addr) : "l"(smem_ptr));
    return addr;
}

__device__ __forceinline__ void sts16(uint32_t addr, unsigned short v) {
    asm volatile("st.shared.u16 [%0], %1;" :: "r"(addr), "h"(v) : "memory");
}
__device__ __forceinline__ void sts64(uint32_t addr, uint32_t a, uint32_t b) {
    asm volatile("st.shared.v2.b32 [%0], {%1, %2};" :: "r"(addr), "r"(a), "r"(b) : "memory");
}

// packed bf16x2 convert: low half = a, high half = b
__device__ __forceinline__ uint32_t cvt_bf16x2(float a, float b) {
    uint32_t d;
    asm("cvt.rn.bf16x2.f32 %0, %1, %2;" : "=r"(d) : "f"(b), "f"(a));
    return d;
}

__device__ __forceinline__ void ldmx4(uint32_t* r, uint32_t addr) {
    asm volatile("ldmatrix.sync.aligned.m8n8.x4.shared.b16 {%0,%1,%2,%3}, [%4];"
                 : "=r"(r[0]), "=r"(r[1]), "=r"(r[2]), "=r"(r[3]) : "r"(addr));
}

__device__ __forceinline__ void mma_bf16(float* d, const uint32_t* a,
                                         uint32_t b0, uint32_t b1) {
    asm volatile(
        "mma.sync.aligned.m16n8k16.row.col.f32.bf16.bf16.f32 "
        "{%0,%1,%2,%3}, {%4,%5,%6,%7}, {%8,%9}, {%0,%1,%2,%3};"
        : "+f"(d[0]), "+f"(d[1]), "+f"(d[2]), "+f"(d[3])
        : "r"(a[0]), "r"(a[1]), "r"(a[2]), "r"(a[3]), "r"(b0), "r"(b1));
}

// ============================================================================
// bf16x3 mma.sync GEMM:  C[m,n] = alpha * sum_k A[m,k] * Bop[k,n]
//   B_IS_KN = true : Bm stored [K, N] row-major  (NN)
//   B_IS_KN = false: Bm stored [N, K] row-major  (NT)
// CTA computes 128x128; 256 threads; K multiple of 32.
// smem tiles: [row][k] bf16, 128 rows x 32 k, row pitch 80B (ldmatrix
// conflict-free: 5 x 16B-unit stride permutes units mod 8).
// ============================================================================
#define KC       32
#define A_PITCH  80
#define TILE_B   (128 * A_PITCH)       // 10240 B per matrix (hi or lo)
#define STAGE_B  (4 * TILE_B)          // Ahi|Alo|Bhi|Blo = 40960 B
#define GEMM_SMEM (2 * STAGE_B)        // 81920 B (double buffered)

// --- global loads (prefetch into registers) ---
__device__ __forceinline__ void ldg_kmajor(const float* __restrict__ P, int ld,
                                           int r0, int k0, int tid, float4* pf) {
#pragma unroll
    for (int i = 0; i < 4; i++) {
        int idx = tid + i * 256;         // 1024 float4 units (128 rows x 8)
        int r   = idx >> 3;
        int c4  = (idx & 7) << 2;
        pf[i] = *reinterpret_cast<const float4*>(&P[(size_t)(r0 + r) * ld + k0 + c4]);
    }
}
__device__ __forceinline__ void ldg_kn(const float* __restrict__ P, int ld,
                                       int n0, int k0, int tid, float2* pf) {
#pragma unroll
    for (int i = 0; i < 8; i++) {
        int u  = tid + i * 256;          // 2048 float2 units (32 k x 64)
        int kk = u >> 6;
        int n2 = u & 63;
        pf[i] = *reinterpret_cast<const float2*>(&P[(size_t)(k0 + kk) * ld + n0 + (n2 << 1)]);
    }
}

// --- convert + store to smem hi/lo tiles ---
__device__ __forceinline__ void sts_kmajor(uint32_t shi, int tid, const float4* pf) {
#pragma unroll
    for (int i = 0; i < 4; i++) {
        int idx = tid + i * 256;
        int r   = idx >> 3;
        int c4  = (idx & 7) << 2;
        float4 v = pf[i];
        uint32_t x0 = __float_as_uint(v.x), x1 = __float_as_uint(v.y);
        uint32_t x2 = __float_as_uint(v.z), x3 = __float_as_uint(v.w);
        uint32_t hi01 = __byte_perm(x0, x1, 0x7632);
        uint32_t hi23 = __byte_perm(x2, x3, 0x7632);
        float l0 = v.x - __uint_as_float(x0 & 0xFFFF0000u);
        float l1 = v.y - __uint_as_float(x1 & 0xFFFF0000u);
        float l2 = v.z - __uint_as_float(x2 & 0xFFFF0000u);
        float l3 = v.w - __uint_as_float(x3 & 0xFFFF0000u);
        uint32_t off = (uint32_t)(r * A_PITCH + (c4 << 1));
        sts64(shi + off, hi01, hi23);
        sts64(shi + TILE_B + off, cvt_bf16x2(l0, l1), cvt_bf16x2(l2, l3));
    }
}
__device__ __forceinline__ void sts_kn(uint32_t bhi, int tid, const float2* pf) {
#pragma unroll
    for (int i = 0; i < 8; i++) {
        int u  = tid + i * 256;
        int kk = u >> 6;
        int n2 = u & 63;
        float2 v = pf[i];
        uint32_t x0 = __float_as_uint(v.x), x1 = __float_as_uint(v.y);
        float l0 = v.x - __uint_as_float(x0 & 0xFFFF0000u);
        float l1 = v.y - __uint_as_float(x1 & 0xFFFF0000u);
        uint32_t lop = cvt_bf16x2(l0, l1);
        uint32_t off0 = (uint32_t)((2 * n2) * A_PITCH + (kk << 1));
        uint32_t off1 = off0 + A_PITCH;
        sts16(bhi + off0, (unsigned short)(x0 >> 16));
        sts16(bhi + off1, (unsigned short)(x1 >> 16));
        sts16(bhi + TILE_B + off0, (unsigned short)(lop & 0xFFFFu));
        sts16(bhi + TILE_B + off1, (unsigned short)(lop >> 16));
    }
}

// --- one 32-k chunk of MMAs from smem stage ---
__device__ __forceinline__ void compute_chunk(uint32_t st, int lane, int wm, int wn,
                                              float acc[4][4][4]) {
    const int r15 = lane & 15;
    const uint32_t kb_lane = (uint32_t)(((lane >> 4) << 3) << 1);  // +8 k for hi half-warp
#pragma unroll
    for (int kk = 0; kk < 2; kk++) {
        uint32_t ahi[4][4], alo[4][4], bh[2][4], bl[2][4];
        const uint32_t kb = (uint32_t)(kk * 32) + kb_lane;         // (kk*16)*2 bytes
#pragma unroll
        for (int mt = 0; mt < 4; mt++) {
            uint32_t ad = st + (uint32_t)((wm + mt * 16 + r15) * A_PITCH) + kb;
            ldmx4(ahi[mt], ad);
            ldmx4(alo[mt], ad + TILE_B);
        }
#pragma unroll
        for (int n2 = 0; n2 < 2; n2++) {
            uint32_t bd = st + 2 * TILE_B +
                          (uint32_t)((wn + n2 * 16 + r15) * A_PITCH) + kb;
            ldmx4(bh[n2], bd);
            ldmx4(bl[n2], bd + TILE_B);
        }
#pragma unroll
        for (int mt = 0; mt < 4; mt++)
#pragma unroll
            for (int nt = 0; nt < 4; nt++) {
                const int n2 = nt >> 1, s = nt & 1;
                mma_bf16(acc[mt][nt], ahi[mt], bh[n2][s], bh[n2][2 + s]);
                mma_bf16(acc[mt][nt], ahi[mt], bl[n2][s], bl[n2][2 + s]);
                mma_bf16(acc[mt][nt], alo[mt], bh[n2][s], bh[n2][2 + s]);
            }
    }
}

template <bool B_IS_KN>
__global__ __launch_bounds__(256, 1)
void gemm_bf16x3(const float* __restrict__ A, const float* __restrict__ Bm,
                 float* __restrict__ C, int K, int lda, int ldb, int ldc,
                 long long sA, long long sB, long long sC, float alpha)
{
    extern __shared__ char smem_raw[];
    const uint32_t smem = smem_to_u32(smem_raw);

    const int tid  = threadIdx.x;
    const int lane = tid & 31;
    const int w    = tid >> 5;
    const int wm   = (w & 1) * 64;
    const int wn   = (w >> 1) * 32;

    const int bz = blockIdx.z;
    A  += (size_t)bz * sA;
    Bm += (size_t)bz * sB;
    C  += (size_t)bz * sC;
    const int row0 = blockIdx.y * 128;
    const int col0 = blockIdx.x * 128;

    float acc[4][4][4];
#pragma unroll
    for (int i = 0; i < 4; i++)
#pragma unroll
        for (int j = 0; j < 4; j++)
#pragma unroll
            for (int q = 0; q < 4; q++) acc[i][j][q] = 0.0f;

    float4 apf[4];
    float4 bpf4[4];
    float2 bpf2[8];

    // prologue: chunk 0 -> stage 0
    ldg_kmajor(A, lda, row0, 0, tid, apf);
    if (B_IS_KN) ldg_kn(Bm, ldb, col0, 0, tid, bpf2);
    else         ldg_kmajor(Bm, ldb, col0, 0, tid, bpf4);
    sts_kmajor(smem, tid, apf);
    if (B_IS_KN) sts_kn(smem + 2 * TILE_B, tid, bpf2);
    else         sts_kmajor(smem + 2 * TILE_B, tid, bpf4);
    __syncthreads();

    const int nch = K / KC;
#pragma unroll 1
    for (int c = 0; c < nch; c++) {
        const bool more = (c + 1 < nch);
        if (more) {
            const int k0 = (c + 1) * KC;
            ldg_kmajor(A, lda, row0, k0, tid, apf);
            if (B_IS_KN) ldg_kn(Bm, ldb, col0, k0, tid, bpf2);
            else         ldg_kmajor(Bm, ldb, col0, k0, tid, bpf4);
        }
        compute_chunk(smem + (uint32_t)(c & 1) * STAGE_B, lane, wm, wn, acc);
        if (more) {
            const uint32_t st = smem + (uint32_t)((c + 1) & 1) * STAGE_B;
            sts_kmajor(st, tid, apf);
            if (B_IS_KN) sts_kn(st + 2 * TILE_B, tid, bpf2);
            else         sts_kmajor(st + 2 * TILE_B, tid, bpf4);
            __syncthreads();
        }
    }

    // epilogue: direct global stores (fragment layout m16n8)
    const int gr = lane >> 2;
    const int tc = (lane & 3) * 2;
#pragma unroll
    for (int mt = 0; mt < 4; mt++) {
#pragma unroll
        for (int nt = 0; nt < 4; nt++) {
            const size_t r = (size_t)(row0 + wm + mt * 16 + gr);
            const int cc   = col0 + wn + nt * 8 + tc;
            float2 v0, v1;
            v0.x = acc[mt][nt][0] * alpha; v0.y = acc[mt][nt][1] * alpha;
            v1.x = acc[mt][nt][2] * alpha; v1.y = acc[mt][nt][3] * alpha;
            *reinterpret_cast<float2*>(&C[r * ldc + cc])       = v0;
            *reinterpret_cast<float2*>(&C[(r + 8) * ldc + cc]) = v1;
        }
    }
}

// ---------------------------------------------------------------------------
// Row softmax over rows of length SEQ (2048). One block (256 threads) per row.
// ---------------------------------------------------------------------------
__global__ __launch_bounds__(256)
void softmax_rows_kernel(float* __restrict__ S)
{
    const size_t row = blockIdx.x;
    float* p = S + row * (size_t)SEQ;
    const int tid = threadIdx.x;

    __shared__ float red[256];

    float vals[SEQ / 256];
    float m = -INFINITY;
#pragma unroll
    for (int i = 0; i < SEQ / 256; i++) {
        vals[i] = p[tid + i * 256];
        m = fmaxf(m, vals[i]);
    }
    red[tid] = m;
    __syncthreads();
    for (int s = 128; s > 0; s >>= 1) {
        if (tid < s) red[tid] = fmaxf(red[tid], red[tid + s]);
        __syncthreads();
    }
    m = red[0];
    __syncthreads();

    float sum = 0.0f;
#pragma unroll
    for (int i = 0; i < SEQ / 256; i++) {
        vals[i] = expf(vals[i] - m);
        sum += vals[i];
    }
    red[tid] = sum;
    __syncthreads();
    for (int s = 128; s > 0; s >>= 1) {
        if (tid < s) red[tid] += red[tid + s];
        __syncthreads();
    }
    const float inv = 1.0f / red[0];

#pragma unroll
    for (int i = 0; i < SEQ / 256; i++) {
        p[tid + i * 256] = vals[i] * inv;
    }
}

// ---------------------------------------------------------------------------
extern "C" void kernel_launch(void* const* d_in, const int* in_sizes, int n_in,
                              void* d_out, int out_size)
{
    const float* X = (const float*)d_in[0];   // [B*S, E]
    const float* W = (const float*)d_in[1];   // [E, 3E]
    float* out = (float*)d_out;               // [B*S, E]

    float* qkv = nullptr;
    float* scores = nullptr;
    cudaGetSymbolAddress((void**)&qkv, g_qkv);
    cudaGetSymbolAddress((void**)&scores, g_scores);

    cudaFuncSetAttribute(gemm_bf16x3<true>,
                         cudaFuncAttributeMaxDynamicSharedMemorySize, GEMM_SMEM);
    cudaFuncSetAttribute(gemm_bf16x3<false>,
                         cudaFuncAttributeMaxDynamicSharedMemorySize, GEMM_SMEM);

    const float scale = 1.0f / 32.0f;  // 1/sqrt(1024)

    // 1) QKV = X @ W      M=8192, N=3072, K=1024   (B is [K,N])
    {
        dim3 grid(THREE_E / 128, (BATCH * SEQ) / 128, 1);
        gemm_bf16x3<true><<<grid, 256, GEMM_SMEM>>>(
            X, W, qkv, EMBED,
            EMBED, THREE_E, THREE_E,
            0LL, 0LL, 0LL, 1.0f);
    }

    // 2) scores[b] = scale * Q[b] @ K[b]^T   M=N=2048, K=1024  (B is [N,K])
    {
        dim3 grid(SEQ / 128, SEQ / 128, BATCH);
        gemm_bf16x3<false><<<grid, 256, GEMM_SMEM>>>(
            qkv /*Q*/, qkv + EMBED /*K*/, scores, EMBED,
            THREE_E, THREE_E, SEQ,
            (long long)SEQ * THREE_E, (long long)SEQ * THREE_E,
            (long long)SEQ * SEQ, scale);
    }

    // 3) softmax over rows of scores
    softmax_rows_kernel<<<BATCH * SEQ, 256>>>(scores);

    // 4) out[b] = P[b] @ V[b]   M=2048, N=1024, K=2048  (B is [K,N])
    {
        dim3 grid(EMBED / 128, SEQ / 128, BATCH);
        gemm_bf16x3<true><<<grid, 256, GEMM_SMEM>>>(
            scores, qkv + 2 * EMBED /*V*/, out, SEQ,
            SEQ, THREE_E, EMBED,
            (long long)SEQ * SEQ, (long long)SEQ * THREE_E,
            (long long)SEQ * EMBED, 1.0f);
    }
}

// round 4
// speedup vs baseline: 1.7731x; 1.0598x over previous
#include <cuda_runtime.h>
#include <cuda_bf16.h>
#include <cstdint>
#include <math.h>

// Problem shape (fixed):
//   hidden_states [4, 2048, 1024] f32, W_qkv [1024, 3072] f32 -> out [4, 2048, 1024] f32
#define BATCH   4
#define SEQ     2048
#define EMBED   1024
#define THREE_E 3072
#define BS      (BATCH * SEQ)

// ---------------------------------------------------------------------------
// Scratch (device globals; allocation anywhere is forbidden)
// ---------------------------------------------------------------------------
__device__ __nv_bfloat16 g_Xhi[(size_t)BS * EMBED];
__device__ __nv_bfloat16 g_Xlo[(size_t)BS * EMBED];
__device__ __nv_bfloat16 g_Wthi[(size_t)THREE_E * EMBED];   // W transposed [3E, E]
__device__ __nv_bfloat16 g_Wtlo[(size_t)THREE_E * EMBED];
__device__ __nv_bfloat16 g_qkvhi[(size_t)BS * THREE_E];
__device__ __nv_bfloat16 g_qkvlo[(size_t)BS * THREE_E];
__device__ __nv_bfloat16 g_vThi[(size_t)BATCH * EMBED * SEQ];  // V^T [b][e][s]
__device__ __nv_bfloat16 g_vTlo[(size_t)BATCH * EMBED * SEQ];
__device__ float         g_scores[(size_t)BATCH * SEQ * SEQ];
__device__ __nv_bfloat16 g_phi[(size_t)BATCH * SEQ * SEQ];
__device__ __nv_bfloat16 g_plo[(size_t)BATCH * SEQ * SEQ];

// ---------------------------------------------------------------------------
// helpers
// ---------------------------------------------------------------------------
__device__ __forceinline__ uint32_t smem_to_u32(const void* smem_ptr) {
    uint32_t addr;
    asm("{ .reg .u64 tmp; cvta.to.shared.u64 tmp, %1; cvt.u32.u64 %0, tmp; }"
        : "=r"(addr) : "l"(smem_ptr));
    return addr;
}

// packed bf16x2 convert: low half = a, high half = b
__device__ __forceinline__ uint32_t cvt_bf16x2(float a, float b) {
    uint32_t d;
    asm("cvt.rn.bf16x2.f32 %0, %1, %2;" : "=r"(d) : "f"(b), "f"(a));
    return d;
}

__device__ __forceinline__ void ldmx4(uint32_t* r, uint32_t addr) {
    asm volatile("ldmatrix.sync.aligned.m8n8.x4.shared.b16 {%0,%1,%2,%3}, [%4];"
                 : "=r"(r[0]), "=r"(r[1]), "=r"(r[2]), "=r"(r[3]) : "r"(addr));
}

__device__ __forceinline__ void mma_bf16(float* d, const uint32_t* a,
                                         uint32_t b0, uint32_t b1) {
    asm volatile(
        "mma.sync.aligned.m16n8k16.row.col.f32.bf16.bf16.f32 "
        "{%0,%1,%2,%3}, {%4,%5,%6,%7}, {%8,%9}, {%0,%1,%2,%3};"
        : "+f"(d[0]), "+f"(d[1]), "+f"(d[2]), "+f"(d[3])
        : "r"(a[0]), "r"(a[1]), "r"(a[2]), "r"(a[3]), "r"(b0), "r"(b1));
}

#define CP16(dst, src) \
    asm volatile("{ .reg .u64 g; cvta.to.global.u64 g, %1; " \
                 "cp.async.cg.shared.global [%0], [g], 16; }" \
                 :: "r"(dst), "l"(src) : "memory")
#define CP_COMMIT() asm volatile("cp.async.commit_group;" ::: "memory")
#define CP_WAIT1()  asm volatile("cp.async.wait_group 1;" ::: "memory")

// ---------------------------------------------------------------------------
// NT GEMM (bf16x3): C[m,n] = alpha * sum_k A[m,k]*B[n,k]
// A,B given as hi/lo bf16 pairs, both K-major. CTA 128x128, 256 thr, KC=32.
// smem tile per matrix: 128 rows x 32 bf16, 64B pitch, XOR swizzle
//   unit(row,ku) = (ku ^ (row>>1)) & 3;  conflict-free for ldmatrix + cp.async
// ---------------------------------------------------------------------------
#define KC       32
#define MTILE_B  8192                 // 128 * 64B
#define STAGE_B  (4 * MTILE_B)        // Ahi|Alo|Bhi|Blo = 32 KB
#define GEMM_SMEM (2 * STAGE_B + 128) // double buffer + align pad

__device__ __forceinline__ uint32_t swz(uint32_t row, uint32_t ku) {
    return row * 64 + (((ku ^ (row >> 1)) & 3u) << 4);
}

__device__ __forceinline__ void cp_pair(const __nv_bfloat16* __restrict__ hi,
                                        const __nv_bfloat16* __restrict__ lo,
                                        int ld, int r0, int k0,
                                        uint32_t dst, int tid) {
#pragma unroll
    for (int i = 0; i < 2; i++) {
        const int idx = tid + i * 256;          // 0..511
        const uint32_t row = (uint32_t)idx >> 2;
        const uint32_t ku  = (uint32_t)idx & 3u;
        const size_t off = (size_t)(r0 + (int)row) * ld + k0 + (int)(ku * 8);
        const uint32_t d = dst + swz(row, ku);
        CP16(d,            (const void*)(hi + off));
        CP16(d + MTILE_B,  (const void*)(lo + off));
    }
}

__device__ __forceinline__ void compute_chunk(uint32_t st, int lane, int wm, int wn,
                                              float acc[4][4][4]) {
    const int r15 = lane & 15;
    const int kuh = lane >> 4;                  // 0/1: +8 k for hi half-warp
#pragma unroll
    for (int kk = 0; kk < 2; kk++) {
        const uint32_t ku = (uint32_t)(kk * 2 + kuh);
        uint32_t ahi[4][4], alo[4][4], bh[2][4], bl[2][4];
#pragma unroll
        for (int mt = 0; mt < 4; mt++) {
            const uint32_t row = (uint32_t)(wm + mt * 16 + r15);
            const uint32_t ad = st + swz(row, ku);
            ldmx4(ahi[mt], ad);
            ldmx4(alo[mt], ad + MTILE_B);
        }
#pragma unroll
        for (int n2 = 0; n2 < 2; n2++) {
            const uint32_t row = (uint32_t)(wn + n2 * 16 + r15);
            const uint32_t bd = st + 2 * MTILE_B + swz(row, ku);
            ldmx4(bh[n2], bd);
            ldmx4(bl[n2], bd + MTILE_B);
        }
#pragma unroll
        for (int mt = 0; mt < 4; mt++)
#pragma unroll
            for (int nt = 0; nt < 4; nt++) {
                const int n2 = nt >> 1, s = nt & 1;
                mma_bf16(acc[mt][nt], ahi[mt], bh[n2][s], bh[n2][2 + s]);
                mma_bf16(acc[mt][nt], ahi[mt], bl[n2][s], bl[n2][2 + s]);
                mma_bf16(acc[mt][nt], alo[mt], bh[n2][s], bh[n2][2 + s]);
            }
    }
}

// mode 0: write C fp32.  mode 1: write Chi/Clo bf16 hi/lo pairs.
__global__ __launch_bounds__(256, 2)
void gemm_nt(const __nv_bfloat16* __restrict__ Ahi, const __nv_bfloat16* __restrict__ Alo,
             const __nv_bfloat16* __restrict__ Bhi, const __nv_bfloat16* __restrict__ Blo,
             float* __restrict__ C, __nv_bfloat16* __restrict__ Chi,
             __nv_bfloat16* __restrict__ Clo,
             int K, int lda, int ldb, int ldc,
             long long sA, long long sB, long long sC, float alpha, int mode)
{
    extern __shared__ char smem_raw[];
    const uint32_t smem = (smem_to_u32(smem_raw) + 127u) & ~127u;

    const int tid  = threadIdx.x;
    const int lane = tid & 31;
    const int w    = tid >> 5;
    const int wm   = (w & 1) * 64;
    const int wn   = (w >> 1) * 32;

    const int bz = blockIdx.z;
    Ahi += (size_t)bz * sA;  Alo += (size_t)bz * sA;
    Bhi += (size_t)bz * sB;  Blo += (size_t)bz * sB;
    const size_t cofs = (size_t)bz * sC;
    const int row0 = blockIdx.y * 128;
    const int col0 = blockIdx.x * 128;

    float acc[4][4][4];
#pragma unroll
    for (int i = 0; i < 4; i++)
#pragma unroll
        for (int j = 0; j < 4; j++)
#pragma unroll
            for (int q = 0; q < 4; q++) acc[i][j][q] = 0.0f;

    // prologue: chunks 0 and 1
    cp_pair(Ahi, Alo, lda, row0, 0, smem, tid);
    cp_pair(Bhi, Blo, ldb, col0, 0, smem + 2 * MTILE_B, tid);
    CP_COMMIT();
    cp_pair(Ahi, Alo, lda, row0, KC, smem + STAGE_B, tid);
    cp_pair(Bhi, Blo, ldb, col0, KC, smem + STAGE_B + 2 * MTILE_B, tid);
    CP_COMMIT();

    const int nch = K / KC;
#pragma unroll 1
    for (int c = 0; c < nch; c++) {
        CP_WAIT1();
        __syncthreads();
        compute_chunk(smem + (uint32_t)(c & 1) * STAGE_B, lane, wm, wn, acc);
        __syncthreads();
        if (c + 2 < nch) {
            const int k0 = (c + 2) * KC;
            const uint32_t st = smem + (uint32_t)(c & 1) * STAGE_B;
            cp_pair(Ahi, Alo, lda, row0, k0, st, tid);
            cp_pair(Bhi, Blo, ldb, col0, k0, st + 2 * MTILE_B, tid);
        }
        CP_COMMIT();
    }

    // epilogue
    const int gr = lane >> 2;
    const int tc = (lane & 3) * 2;
#pragma unroll
    for (int mt = 0; mt < 4; mt++) {
#pragma unroll
        for (int nt = 0; nt < 4; nt++) {
            const size_t r0e = (size_t)(row0 + wm + mt * 16 + gr);
            const int cc = col0 + wn + nt * 8 + tc;
            float v0 = acc[mt][nt][0] * alpha, v1 = acc[mt][nt][1] * alpha;
            float v2 = acc[mt][nt][2] * alpha, v3 = acc[mt][nt][3] * alpha;
            if (mode == 0) {
                float2 a = make_float2(v0, v1), b = make_float2(v2, v3);
                *reinterpret_cast<float2*>(&C[cofs + r0e * ldc + cc])       = a;
                *reinterpret_cast<float2*>(&C[cofs + (r0e + 8) * ldc + cc]) = b;
            } else {
                uint32_t x0 = __float_as_uint(v0), x1 = __float_as_uint(v1);
                uint32_t x2 = __float_as_uint(v2), x3 = __float_as_uint(v3);
                uint32_t h01 = __byte_perm(x0, x1, 0x7632);
                uint32_t h23 = __byte_perm(x2, x3, 0x7632);
                float l0 = v0 - __uint_as_float(x0 & 0xFFFF0000u);
                float l1 = v1 - __uint_as_float(x1 & 0xFFFF0000u);
                float l2 = v2 - __uint_as_float(x2 & 0xFFFF0000u);
                float l3 = v3 - __uint_as_float(x3 & 0xFFFF0000u);
                *reinterpret_cast<uint32_t*>(&Chi[cofs + r0e * ldc + cc])       = h01;
                *reinterpret_cast<uint32_t*>(&Chi[cofs + (r0e + 8) * ldc + cc]) = h23;
                *reinterpret_cast<uint32_t*>(&Clo[cofs + r0e * ldc + cc])       = cvt_bf16x2(l0, l1);
                *reinterpret_cast<uint32_t*>(&Clo[cofs + (r0e + 8) * ldc + cc]) = cvt_bf16x2(l2, l3);
            }
        }
    }
}

// ---------------------------------------------------------------------------
// elementwise fp32 -> bf16 hi/lo
// ---------------------------------------------------------------------------
__global__ __launch_bounds__(256)
void convert_hilo(const float* __restrict__ in, __nv_bfloat16* __restrict__ hi,
                  __nv_bfloat16* __restrict__ lo)
{
    const size_t i4 = ((size_t)blockIdx.x * 256 + threadIdx.x) * 4;
    float4 v = *reinterpret_cast<const float4*>(in + i4);
    uint32_t x0 = __float_as_uint(v.x), x1 = __float_as_uint(v.y);
    uint32_t x2 = __float_as_uint(v.z), x3 = __float_as_uint(v.w);
    uint2 h;
    h.x = __byte_perm(x0, x1, 0x7632);
    h.y = __byte_perm(x2, x3, 0x7632);
    float l0 = v.x - __uint_as_float(x0 & 0xFFFF0000u);
    float l1 = v.y - __uint_as_float(x1 & 0xFFFF0000u);
    float l2 = v.z - __uint_as_float(x2 & 0xFFFF0000u);
    float l3 = v.w - __uint_as_float(x3 & 0xFFFF0000u);
    uint2 l;
    l.x = cvt_bf16x2(l0, l1);
    l.y = cvt_bf16x2(l2, l3);
    *reinterpret_cast<uint2*>(hi + i4) = h;
    *reinterpret_cast<uint2*>(lo + i4) = l;
}

// ---------------------------------------------------------------------------
// transpose + convert: W [E, 3E] f32 -> Wt hi/lo [3E, E] bf16
// ---------------------------------------------------------------------------
__global__ __launch_bounds__(256)
void transpose_convert_w(const float* __restrict__ in,
                         __nv_bfloat16* __restrict__ ohi,
                         __nv_bfloat16* __restrict__ olo)
{
    __shared__ float t[32][33];
    const int c0 = blockIdx.x * 32;   // over 3E
    const int r0 = blockIdx.y * 32;   // over E
    const int tx = threadIdx.x & 31;
    const int ty = threadIdx.x >> 5;  // 0..7
#pragma unroll
    for (int j = 0; j < 4; j++)
        t[ty + j * 8][tx] = in[(size_t)(r0 + ty + j * 8) * THREE_E + c0 + tx];
    __syncthreads();
#pragma unroll
    for (int j = 0; j < 4; j++) {
        const float v = t[tx][ty + j * 8];
        const uint32_t xb = __float_as_uint(v);
        const size_t o = (size_t)(c0 + ty + j * 8) * EMBED + r0 + tx;
        *reinterpret_cast<unsigned short*>(&ohi[o]) = (unsigned short)(xb >> 16);
        olo[o] = __float2bfloat16(v - __uint_as_float(xb & 0xFFFF0000u));
    }
}

// ---------------------------------------------------------------------------
// transpose V part of qkv (hi/lo bf16) -> vT [b][e][s]
// ---------------------------------------------------------------------------
__global__ __launch_bounds__(256)
void transpose_v(const __nv_bfloat16* __restrict__ qh,
                 const __nv_bfloat16* __restrict__ ql,
                 __nv_bfloat16* __restrict__ vh, __nv_bfloat16* __restrict__ vl)
{
    __shared__ unsigned short th[32][34];
    __shared__ unsigned short tl[32][34];
    const int b  = blockIdx.z;
    const int s0 = blockIdx.x * 32;
    const int e0 = blockIdx.y * 32;
    const int tx = threadIdx.x & 31;
    const int ty = threadIdx.x >> 5;
#pragma unroll
    for (int j = 0; j < 4; j++) {
        const size_t o = (size_t)(b * SEQ + s0 + ty + j * 8) * THREE_E + 2 * EMBED + e0 + tx;
        th[ty + j * 8][tx] = *reinterpret_cast<const unsigned short*>(&qh[o]);
        tl[ty + j * 8][tx] = *reinterpret_cast<const unsigned short*>(&ql[o]);
    }
    __syncthreads();
#pragma unroll
    for (int j = 0; j < 4; j++) {
        const size_t o = (size_t)b * EMBED * SEQ + (size_t)(e0 + ty + j * 8) * SEQ + s0 + tx;
        *reinterpret_cast<unsigned short*>(&vh[o]) = th[tx][ty + j * 8];
        *reinterpret_cast<unsigned short*>(&vl[o]) = tl[tx][ty + j * 8];
    }
}

// ---------------------------------------------------------------------------
// softmax over rows of scores; writes p as bf16 hi/lo
// ---------------------------------------------------------------------------
__global__ __launch_bounds__(256)
void softmax_rows_kernel(const float* __restrict__ S,
                         __nv_bfloat16* __restrict__ phi,
                         __nv_bfloat16* __restrict__ plo)
{
    const size_t row = blockIdx.x;
    const float* p = S + row * (size_t)SEQ;
    const int tid = threadIdx.x;

    __shared__ float red[256];

    float vals[SEQ / 256];
    float m = -INFINITY;
#pragma unroll
    for (int i = 0; i < SEQ / 256; i++) {
        vals[i] = p[tid + i * 256];
        m = fmaxf(m, vals[i]);
    }
    red[tid] = m;
    __syncthreads();
    for (int s = 128; s > 0; s >>= 1) {
        if (tid < s) red[tid] = fmaxf(red[tid], red[tid + s]);
        __syncthreads();
    }
    m = red[0];
    __syncthreads();

    float sum = 0.0f;
#pragma unroll
    for (int i = 0; i < SEQ / 256; i++) {
        vals[i] = expf(vals[i] - m);
        sum += vals[i];
    }
    red[tid] = sum;
    __syncthreads();
    for (int s = 128; s > 0; s >>= 1) {
        if (tid < s) red[tid] += red[tid + s];
        __syncthreads();
    }
    const float inv = 1.0f / red[0];

#pragma unroll
    for (int i = 0; i < SEQ / 256; i++) {
        const float v = vals[i] * inv;
        const uint32_t xb = __float_as_uint(v);
        const size_t o = row * (size_t)SEQ + tid + i * 256;
        *reinterpret_cast<unsigned short*>(&phi[o]) = (unsigned short)(xb >> 16);
        plo[o] = __float2bfloat16(v - __uint_as_float(xb & 0xFFFF0000u));
    }
}

// ---------------------------------------------------------------------------
extern "C" void kernel_launch(void* const* d_in, const int* in_sizes, int n_in,
                              void* d_out, int out_size)
{
    const float* X = (const float*)d_in[0];   // [B*S, E]
    const float* W = (const float*)d_in[1];   // [E, 3E]
    float* out = (float*)d_out;               // [B*S, E]

    __nv_bfloat16 *Xhi, *Xlo, *Wthi, *Wtlo, *qkvhi, *qkvlo, *vThi, *vTlo, *phi, *plo;
    float* scores;
    cudaGetSymbolAddress((void**)&Xhi, g_Xhi);
    cudaGetSymbolAddress((void**)&Xlo, g_Xlo);
    cudaGetSymbolAddress((void**)&Wthi, g_Wthi);
    cudaGetSymbolAddress((void**)&Wtlo, g_Wtlo);
    cudaGetSymbolAddress((void**)&qkvhi, g_qkvhi);
    cudaGetSymbolAddress((void**)&qkvlo, g_qkvlo);
    cudaGetSymbolAddress((void**)&vThi, g_vThi);
    cudaGetSymbolAddress((void**)&vTlo, g_vTlo);
    cudaGetSymbolAddress((void**)&scores, g_scores);
    cudaGetSymbolAddress((void**)&phi, g_phi);
    cudaGetSymbolAddress((void**)&plo, g_plo);

    cudaFuncSetAttribute(gemm_nt, cudaFuncAttributeMaxDynamicSharedMemorySize, GEMM_SMEM);

    const float scale = 1.0f / 32.0f;  // 1/sqrt(1024)

    // 0a) X -> bf16 hi/lo
    convert_hilo<<<(size_t)BS * EMBED / 1024, 256>>>(X, Xhi, Xlo);
    // 0b) W -> Wt bf16 hi/lo (transposed)
    transpose_convert_w<<<dim3(THREE_E / 32, EMBED / 32), 256>>>(W, Wthi, Wtlo);

    // 1) QKV = X @ W : NT with Wt.  M=8192, N=3072, K=1024 -> qkv hi/lo
    gemm_nt<<<dim3(THREE_E / 128, BS / 128, 1), 256, GEMM_SMEM>>>(
        Xhi, Xlo, Wthi, Wtlo, nullptr, qkvhi, qkvlo,
        EMBED, EMBED, EMBED, THREE_E, 0LL, 0LL, 0LL, 1.0f, 1);

    // 1b) V part -> vT hi/lo
    transpose_v<<<dim3(SEQ / 32, EMBED / 32, BATCH), 256>>>(qkvhi, qkvlo, vThi, vTlo);

    // 2) scores = scale * Q @ K^T : NT.  M=N=2048, K=1024, batched
    gemm_nt<<<dim3(SEQ / 128, SEQ / 128, BATCH), 256, GEMM_SMEM>>>(
        qkvhi, qkvlo, qkvhi + EMBED, qkvlo + EMBED, scores, nullptr, nullptr,
        EMBED, THREE_E, THREE_E, SEQ,
        (long long)SEQ * THREE_E, (long long)SEQ * THREE_E,
        (long long)SEQ * SEQ, scale, 0);

    // 3) softmax -> p hi/lo
    softmax_rows_kernel<<<BS, 256>>>(scores, phi, plo);

    // 4) out = P @ V : NT with vT.  M=2048, N=1024, K=2048, batched
    gemm_nt<<<dim3(EMBED / 128, SEQ / 128, BATCH), 256, GEMM_SMEM>>>(
        phi, plo, vThi, vTlo, out, nullptr, nullptr,
        SEQ, SEQ, SEQ, EMBED,
        (long long)SEQ * SEQ, (long long)EMBED * SEQ,
        (long long)SEQ * EMBED, 1.0f, 0);
}

// round 5
// speedup vs baseline: 2.8526x; 1.6088x over previous
#include <cuda_runtime.h>
#include <cuda_bf16.h>
#include <cstdint>
#include <math.h>

// Problem shape (fixed):
//   hidden_states [4, 2048, 1024] f32, W_qkv [1024, 3072] f32 -> out [4, 2048, 1024] f32
#define BATCH   4
#define SEQ     2048
#define EMBED   1024
#define THREE_E 3072
#define BS      (BATCH * SEQ)

// ---------------------------------------------------------------------------
// Scratch (device globals; allocation anywhere is forbidden)
// ---------------------------------------------------------------------------
__device__ __nv_bfloat16 g_Xhi[(size_t)BS * EMBED];
__device__ __nv_bfloat16 g_Xlo[(size_t)BS * EMBED];
__device__ __nv_bfloat16 g_Wthi[(size_t)THREE_E * EMBED];   // W transposed [3E, E]
__device__ __nv_bfloat16 g_Wtlo[(size_t)THREE_E * EMBED];
__device__ __nv_bfloat16 g_qkvhi[(size_t)BS * THREE_E];
__device__ __nv_bfloat16 g_qkvlo[(size_t)BS * THREE_E];
__device__ __nv_bfloat16 g_vThi[(size_t)BATCH * EMBED * SEQ];  // V^T [b][e][s]
__device__ __nv_bfloat16 g_vTlo[(size_t)BATCH * EMBED * SEQ];
__device__ float         g_scores[(size_t)BATCH * SEQ * SEQ];
__device__ __nv_bfloat16 g_phi[(size_t)BATCH * SEQ * SEQ];
__device__ __nv_bfloat16 g_plo[(size_t)BATCH * SEQ * SEQ];

// ---------------------------------------------------------------------------
// helpers
// ---------------------------------------------------------------------------
__device__ __forceinline__ uint32_t smem_to_u32(const void* smem_ptr) {
    uint32_t addr;
    asm("{ .reg .u64 tmp; cvta.to.shared.u64 tmp, %1; cvt.u32.u64 %0, tmp; }"
        : "=r"(addr) : "l"(smem_ptr));
    return addr;
}

// packed bf16x2 convert: low half = a, high half = b
__device__ __forceinline__ uint32_t cvt_bf16x2(float a, float b) {
    uint32_t d;
    asm("cvt.rn.bf16x2.f32 %0, %1, %2;" : "=r"(d) : "f"(b), "f"(a));
    return d;
}

__device__ __forceinline__ void ldmx4(uint32_t* r, uint32_t addr) {
    asm volatile("ldmatrix.sync.aligned.m8n8.x4.shared.b16 {%0,%1,%2,%3}, [%4];"
                 : "=r"(r[0]), "=r"(r[1]), "=r"(r[2]), "=r"(r[3]) : "r"(addr));
}

__device__ __forceinline__ void mma_bf16(float* d, const uint32_t* a,
                                         uint32_t b0, uint32_t b1) {
    asm volatile(
        "mma.sync.aligned.m16n8k16.row.col.f32.bf16.bf16.f32 "
        "{%0,%1,%2,%3}, {%4,%5,%6,%7}, {%8,%9}, {%0,%1,%2,%3};"
        : "+f"(d[0]), "+f"(d[1]), "+f"(d[2]), "+f"(d[3])
        : "r"(a[0]), "r"(a[1]), "r"(a[2]), "r"(a[3]), "r"(b0), "r"(b1));
}

#define CP16(dst, src) \
    asm volatile("{ .reg .u64 g; cvta.to.global.u64 g, %1; " \
                 "cp.async.cg.shared.global [%0], [g], 16; }" \
                 :: "r"(dst), "l"(src) : "memory")
#define CP_COMMIT() asm volatile("cp.async.commit_group;" ::: "memory")
#define CP_WAIT1()  asm volatile("cp.async.wait_group 1;" ::: "memory")

// ---------------------------------------------------------------------------
// NT GEMM (bf16x3): C[m,n] = alpha * sum_k A[m,k]*B[n,k]
// A,B given as hi/lo bf16 pairs, both K-major. CTA 128x128, 256 thr, KC=32.
// smem tile per matrix: 128 rows x 32 bf16, 64B pitch, XOR swizzle
//   unit(row,ku) = (ku ^ (row>>1)) & 3;  conflict-free for ldmatrix + cp.async
// 3-stage cp.async pipeline; one __syncthreads per chunk.
// ---------------------------------------------------------------------------
#define KC       32
#define MTILE_B  8192                 // 128 * 64B
#define STAGE_B  (4 * MTILE_B)        // Ahi|Alo|Bhi|Blo = 32 KB
#define NSTAGE   3
#define GEMM_SMEM (NSTAGE * STAGE_B + 128)

__device__ __forceinline__ uint32_t swz(uint32_t row, uint32_t ku) {
    return row * 64 + (((ku ^ (row >> 1)) & 3u) << 4);
}

__device__ __forceinline__ void cp_pair(const __nv_bfloat16* __restrict__ hi,
                                        const __nv_bfloat16* __restrict__ lo,
                                        int ld, int r0, int k0,
                                        uint32_t dst, int tid) {
#pragma unroll
    for (int i = 0; i < 2; i++) {
        const int idx = tid + i * 256;          // 0..511
        const uint32_t row = (uint32_t)idx >> 2;
        const uint32_t ku  = (uint32_t)idx & 3u;
        const size_t off = (size_t)(r0 + (int)row) * ld + k0 + (int)(ku * 8);
        const uint32_t d = dst + swz(row, ku);
        CP16(d,            (const void*)(hi + off));
        CP16(d + MTILE_B,  (const void*)(lo + off));
    }
}

// Low-register inner loop: A fragments loaded twice (hi then lo into the SAME
// registers); B hi/lo fragments resident. Live set ~ acc64 + 16 + 4.
__device__ __forceinline__ void compute_chunk(uint32_t st, int lane, int wm, int wn,
                                              float acc[4][4][4]) {
    const int r15 = lane & 15;
    const int kuh = lane >> 4;                  // 0/1: +8 k for hi half-warp
#pragma unroll
    for (int kk = 0; kk < 2; kk++) {
        const uint32_t ku = (uint32_t)(kk * 2 + kuh);
        uint32_t bh[2][4], bl[2][4];
#pragma unroll
        for (int n2 = 0; n2 < 2; n2++) {
            const uint32_t bd = st + 2 * MTILE_B + swz((uint32_t)(wn + n2 * 16 + r15), ku);
            ldmx4(bh[n2], bd);
            ldmx4(bl[n2], bd + MTILE_B);
        }
#pragma unroll
        for (int mt = 0; mt < 4; mt++) {
            const uint32_t ad = st + swz((uint32_t)(wm + mt * 16 + r15), ku);
            uint32_t a[4];
            ldmx4(a, ad);                       // A-hi
#pragma unroll
            for (int nt = 0; nt < 4; nt++) {
                const int n2 = nt >> 1, s = nt & 1;
                mma_bf16(acc[mt][nt], a, bh[n2][s], bh[n2][2 + s]);
                mma_bf16(acc[mt][nt], a, bl[n2][s], bl[n2][2 + s]);
            }
            ldmx4(a, ad + MTILE_B);             // A-lo (reuse regs)
#pragma unroll
            for (int nt = 0; nt < 4; nt++) {
                const int n2 = nt >> 1, s = nt & 1;
                mma_bf16(acc[mt][nt], a, bh[n2][s], bh[n2][2 + s]);
            }
        }
    }
}

// mode 0: write C fp32.  mode 1: write Chi/Clo bf16 hi/lo pairs.
__global__ __launch_bounds__(256, 2)
void gemm_nt(const __nv_bfloat16* __restrict__ Ahi, const __nv_bfloat16* __restrict__ Alo,
             const __nv_bfloat16* __restrict__ Bhi, const __nv_bfloat16* __restrict__ Blo,
             float* __restrict__ C, __nv_bfloat16* __restrict__ Chi,
             __nv_bfloat16* __restrict__ Clo,
             int K, int lda, int ldb, int ldc,
             long long sA, long long sB, long long sC, float alpha, int mode)
{
    extern __shared__ char smem_raw[];
    const uint32_t smem = (smem_to_u32(smem_raw) + 127u) & ~127u;

    const int tid  = threadIdx.x;
    const int lane = tid & 31;
    const int w    = tid >> 5;
    const int wm   = (w & 1) * 64;
    const int wn   = (w >> 1) * 32;

    const int bz = blockIdx.z;
    Ahi += (size_t)bz * sA;  Alo += (size_t)bz * sA;
    Bhi += (size_t)bz * sB;  Blo += (size_t)bz * sB;
    const size_t cofs = (size_t)bz * sC;
    const int row0 = blockIdx.y * 128;
    const int col0 = blockIdx.x * 128;

    float acc[4][4][4];
#pragma unroll
    for (int i = 0; i < 4; i++)
#pragma unroll
        for (int j = 0; j < 4; j++)
#pragma unroll
            for (int q = 0; q < 4; q++) acc[i][j][q] = 0.0f;

    // prologue: chunk 0 -> stage 0, chunk 1 -> stage 1
    cp_pair(Ahi, Alo, lda, row0, 0, smem, tid);
    cp_pair(Bhi, Blo, ldb, col0, 0, smem + 2 * MTILE_B, tid);
    CP_COMMIT();
    cp_pair(Ahi, Alo, lda, row0, KC, smem + STAGE_B, tid);
    cp_pair(Bhi, Blo, ldb, col0, KC, smem + STAGE_B + 2 * MTILE_B, tid);
    CP_COMMIT();

    const int nch = K / KC;
    int cstage = 0;   // stage of current chunk
    int pstage = 2;   // stage for prefetch (chunk c+2)
#pragma unroll 1
    for (int c = 0; c < nch; c++) {
        CP_WAIT1();                // chunk c resident
        __syncthreads();           // all warps done reading stage pstage (chunk c-1 path safe)
        compute_chunk(smem + (uint32_t)cstage * STAGE_B, lane, wm, wn, acc);
        if (c + 2 < nch) {
            const int k0 = (c + 2) * KC;
            const uint32_t st = smem + (uint32_t)pstage * STAGE_B;
            cp_pair(Ahi, Alo, lda, row0, k0, st, tid);
            cp_pair(Bhi, Blo, ldb, col0, k0, st + 2 * MTILE_B, tid);
        }
        CP_COMMIT();
        cstage = (cstage == 2) ? 0 : cstage + 1;
        pstage = (pstage == 2) ? 0 : pstage + 1;
    }

    // epilogue
    const int gr = lane >> 2;
    const int tc = (lane & 3) * 2;
#pragma unroll
    for (int mt = 0; mt < 4; mt++) {
#pragma unroll
        for (int nt = 0; nt < 4; nt++) {
            const size_t r0e = (size_t)(row0 + wm + mt * 16 + gr);
            const int cc = col0 + wn + nt * 8 + tc;
            float v0 = acc[mt][nt][0] * alpha, v1 = acc[mt][nt][1] * alpha;
            float v2 = acc[mt][nt][2] * alpha, v3 = acc[mt][nt][3] * alpha;
            if (mode == 0) {
                float2 a = make_float2(v0, v1), b = make_float2(v2, v3);
                *reinterpret_cast<float2*>(&C[cofs + r0e * ldc + cc])       = a;
                *reinterpret_cast<float2*>(&C[cofs + (r0e + 8) * ldc + cc]) = b;
            } else {
                uint32_t x0 = __float_as_uint(v0), x1 = __float_as_uint(v1);
                uint32_t x2 = __float_as_uint(v2), x3 = __float_as_uint(v3);
                uint32_t h01 = __byte_perm(x0, x1, 0x7632);
                uint32_t h23 = __byte_perm(x2, x3, 0x7632);
                float l0 = v0 - __uint_as_float(x0 & 0xFFFF0000u);
                float l1 = v1 - __uint_as_float(x1 & 0xFFFF0000u);
                float l2 = v2 - __uint_as_float(x2 & 0xFFFF0000u);
                float l3 = v3 - __uint_as_float(x3 & 0xFFFF0000u);
                *reinterpret_cast<uint32_t*>(&Chi[cofs + r0e * ldc + cc])       = h01;
                *reinterpret_cast<uint32_t*>(&Chi[cofs + (r0e + 8) * ldc + cc]) = h23;
                *reinterpret_cast<uint32_t*>(&Clo[cofs + r0e * ldc + cc])       = cvt_bf16x2(l0, l1);
                *reinterpret_cast<uint32_t*>(&Clo[cofs + (r0e + 8) * ldc + cc]) = cvt_bf16x2(l2, l3);
            }
        }
    }
}

// ---------------------------------------------------------------------------
// elementwise fp32 -> bf16 hi/lo
// ---------------------------------------------------------------------------
__global__ __launch_bounds__(256)
void convert_hilo(const float* __restrict__ in, __nv_bfloat16* __restrict__ hi,
                  __nv_bfloat16* __restrict__ lo)
{
    const size_t i4 = ((size_t)blockIdx.x * 256 + threadIdx.x) * 4;
    float4 v = *reinterpret_cast<const float4*>(in + i4);
    uint32_t x0 = __float_as_uint(v.x), x1 = __float_as_uint(v.y);
    uint32_t x2 = __float_as_uint(v.z), x3 = __float_as_uint(v.w);
    uint2 h;
    h.x = __byte_perm(x0, x1, 0x7632);
    h.y = __byte_perm(x2, x3, 0x7632);
    float l0 = v.x - __uint_as_float(x0 & 0xFFFF0000u);
    float l1 = v.y - __uint_as_float(x1 & 0xFFFF0000u);
    float l2 = v.z - __uint_as_float(x2 & 0xFFFF0000u);
    float l3 = v.w - __uint_as_float(x3 & 0xFFFF0000u);
    uint2 l;
    l.x = cvt_bf16x2(l0, l1);
    l.y = cvt_bf16x2(l2, l3);
    *reinterpret_cast<uint2*>(hi + i4) = h;
    *reinterpret_cast<uint2*>(lo + i4) = l;
}

// ---------------------------------------------------------------------------
// transpose + convert: W [E, 3E] f32 -> Wt hi/lo [3E, E] bf16
// ---------------------------------------------------------------------------
__global__ __launch_bounds__(256)
void transpose_convert_w(const float* __restrict__ in,
                         __nv_bfloat16* __restrict__ ohi,
                         __nv_bfloat16* __restrict__ olo)
{
    __shared__ float t[32][33];
    const int c0 = blockIdx.x * 32;   // over 3E
    const int r0 = blockIdx.y * 32;   // over E
    const int tx = threadIdx.x & 31;
    const int ty = threadIdx.x >> 5;  // 0..7
#pragma unroll
    for (int j = 0; j < 4; j++)
        t[ty + j * 8][tx] = in[(size_t)(r0 + ty + j * 8) * THREE_E + c0 + tx];
    __syncthreads();
#pragma unroll
    for (int j = 0; j < 4; j++) {
        const float v = t[tx][ty + j * 8];
        const uint32_t xb = __float_as_uint(v);
        const size_t o = (size_t)(c0 + ty + j * 8) * EMBED + r0 + tx;
        *reinterpret_cast<unsigned short*>(&ohi[o]) = (unsigned short)(xb >> 16);
        olo[o] = __float2bfloat16(v - __uint_as_float(xb & 0xFFFF0000u));
    }
}

// ---------------------------------------------------------------------------
// transpose V part of qkv (hi/lo bf16) -> vT [b][e][s]
// ---------------------------------------------------------------------------
__global__ __launch_bounds__(256)
void transpose_v(const __nv_bfloat16* __restrict__ qh,
                 const __nv_bfloat16* __restrict__ ql,
                 __nv_bfloat16* __restrict__ vh, __nv_bfloat16* __restrict__ vl)
{
    __shared__ unsigned short th[32][34];
    __shared__ unsigned short tl[32][34];
    const int b  = blockIdx.z;
    const int s0 = blockIdx.x * 32;
    const int e0 = blockIdx.y * 32;
    const int tx = threadIdx.x & 31;
    const int ty = threadIdx.x >> 5;
#pragma unroll
    for (int j = 0; j < 4; j++) {
        const size_t o = (size_t)(b * SEQ + s0 + ty + j * 8) * THREE_E + 2 * EMBED + e0 + tx;
        th[ty + j * 8][tx] = *reinterpret_cast<const unsigned short*>(&qh[o]);
        tl[ty + j * 8][tx] = *reinterpret_cast<const unsigned short*>(&ql[o]);
    }
    __syncthreads();
#pragma unroll
    for (int j = 0; j < 4; j++) {
        const size_t o = (size_t)b * EMBED * SEQ + (size_t)(e0 + ty + j * 8) * SEQ + s0 + tx;
        *reinterpret_cast<unsigned short*>(&vh[o]) = th[tx][ty + j * 8];
        *reinterpret_cast<unsigned short*>(&vl[o]) = tl[tx][ty + j * 8];
    }
}

// ---------------------------------------------------------------------------
// softmax over rows of scores; writes p as bf16 hi/lo
// ---------------------------------------------------------------------------
__global__ __launch_bounds__(256)
void softmax_rows_kernel(const float* __restrict__ S,
                         __nv_bfloat16* __restrict__ phi,
                         __nv_bfloat16* __restrict__ plo)
{
    const size_t row = blockIdx.x;
    const float* p = S + row * (size_t)SEQ;
    const int tid = threadIdx.x;

    __shared__ float red[256];

    float vals[SEQ / 256];
    float m = -INFINITY;
#pragma unroll
    for (int i = 0; i < SEQ / 256; i++) {
        vals[i] = p[tid + i * 256];
        m = fmaxf(m, vals[i]);
    }
    red[tid] = m;
    __syncthreads();
    for (int s = 128; s > 0; s >>= 1) {
        if (tid < s) red[tid] = fmaxf(red[tid], red[tid + s]);
        __syncthreads();
    }
    m = red[0];
    __syncthreads();

    float sum = 0.0f;
#pragma unroll
    for (int i = 0; i < SEQ / 256; i++) {
        vals[i] = expf(vals[i] - m);
        sum += vals[i];
    }
    red[tid] = sum;
    __syncthreads();
    for (int s = 128; s > 0; s >>= 1) {
        if (tid < s) red[tid] += red[tid + s];
        __syncthreads();
    }
    const float inv = 1.0f / red[0];

#pragma unroll
    for (int i = 0; i < SEQ / 256; i++) {
        const float v = vals[i] * inv;
        const uint32_t xb = __float_as_uint(v);
        const size_t o = row * (size_t)SEQ + tid + i * 256;
        *reinterpret_cast<unsigned short*>(&phi[o]) = (unsigned short)(xb >> 16);
        plo[o] = __float2bfloat16(v - __uint_as_float(xb & 0xFFFF0000u));
    }
}

// ---------------------------------------------------------------------------
extern "C" void kernel_launch(void* const* d_in, const int* in_sizes, int n_in,
                              void* d_out, int out_size)
{
    const float* X = (const float*)d_in[0];   // [B*S, E]
    const float* W = (const float*)d_in[1];   // [E, 3E]
    float* out = (float*)d_out;               // [B*S, E]

    __nv_bfloat16 *Xhi, *Xlo, *Wthi, *Wtlo, *qkvhi, *qkvlo, *vThi, *vTlo, *phi, *plo;
    float* scores;
    cudaGetSymbolAddress((void**)&Xhi, g_Xhi);
    cudaGetSymbolAddress((void**)&Xlo, g_Xlo);
    cudaGetSymbolAddress((void**)&Wthi, g_Wthi);
    cudaGetSymbolAddress((void**)&Wtlo, g_Wtlo);
    cudaGetSymbolAddress((void**)&qkvhi, g_qkvhi);
    cudaGetSymbolAddress((void**)&qkvlo, g_qkvlo);
    cudaGetSymbolAddress((void**)&vThi, g_vThi);
    cudaGetSymbolAddress((void**)&vTlo, g_vTlo);
    cudaGetSymbolAddress((void**)&scores, g_scores);
    cudaGetSymbolAddress((void**)&phi, g_phi);
    cudaGetSymbolAddress((void**)&plo, g_plo);

    cudaFuncSetAttribute(gemm_nt, cudaFuncAttributeMaxDynamicSharedMemorySize, GEMM_SMEM);

    const float scale = 1.0f / 32.0f;  // 1/sqrt(1024)

    // 0a) X -> bf16 hi/lo
    convert_hilo<<<(size_t)BS * EMBED / 1024, 256>>>(X, Xhi, Xlo);
    // 0b) W -> Wt bf16 hi/lo (transposed)
    transpose_convert_w<<<dim3(THREE_E / 32, EMBED / 32), 256>>>(W, Wthi, Wtlo);

    // 1) QKV = X @ W : NT with Wt.  M=8192, N=3072, K=1024 -> qkv hi/lo
    gemm_nt<<<dim3(THREE_E / 128, BS / 128, 1), 256, GEMM_SMEM>>>(
        Xhi, Xlo, Wthi, Wtlo, nullptr, qkvhi, qkvlo,
        EMBED, EMBED, EMBED, THREE_E, 0LL, 0LL, 0LL, 1.0f, 1);

    // 1b) V part -> vT hi/lo
    transpose_v<<<dim3(SEQ / 32, EMBED / 32, BATCH), 256>>>(qkvhi, qkvlo, vThi, vTlo);

    // 2) scores = scale * Q @ K^T : NT.  M=N=2048, K=1024, batched
    gemm_nt<<<dim3(SEQ / 128, SEQ / 128, BATCH), 256, GEMM_SMEM>>>(
        qkvhi, qkvlo, qkvhi + EMBED, qkvlo + EMBED, scores, nullptr, nullptr,
        EMBED, THREE_E, THREE_E, SEQ,
        (long long)SEQ * THREE_E, (long long)SEQ * THREE_E,
        (long long)SEQ * SEQ, scale, 0);

    // 3) softmax -> p hi/lo
    softmax_rows_kernel<<<BS, 256>>>(scores, phi, plo);

    // 4) out = P @ V : NT with vT.  M=2048, N=1024, K=2048, batched
    gemm_nt<<<dim3(EMBED / 128, SEQ / 128, BATCH), 256, GEMM_SMEM>>>(
        phi, plo, vThi, vTlo, out, nullptr, nullptr,
        SEQ, SEQ, SEQ, EMBED,
        (long long)SEQ * SEQ, (long long)EMBED * SEQ,
        (long long)SEQ * EMBED, 1.0f, 0);
}

// round 6
// speedup vs baseline: 2.9036x; 1.0179x over previous
#include <cuda_runtime.h>
#include <cuda_bf16.h>
#include <cstdint>
#include <math.h>

// Problem shape (fixed):
//   hidden_states [4, 2048, 1024] f32, W_qkv [1024, 3072] f32 -> out [4, 2048, 1024] f32
#define BATCH   4
#define SEQ     2048
#define EMBED   1024
#define THREE_E 3072
#define BS      (BATCH * SEQ)

// ---------------------------------------------------------------------------
// Scratch (device globals; allocation anywhere is forbidden)
// ---------------------------------------------------------------------------
__device__ __nv_bfloat16 g_Xhi[(size_t)BS * EMBED];
__device__ __nv_bfloat16 g_Xlo[(size_t)BS * EMBED];
__device__ __nv_bfloat16 g_Wthi[(size_t)THREE_E * EMBED];   // W transposed [3E, E]
__device__ __nv_bfloat16 g_Wtlo[(size_t)THREE_E * EMBED];
__device__ __nv_bfloat16 g_qkvhi[(size_t)BS * THREE_E];
__device__ __nv_bfloat16 g_qkvlo[(size_t)BS * THREE_E];
__device__ __nv_bfloat16 g_vThi[(size_t)BATCH * EMBED * SEQ];  // V^T [b][e][s]
__device__ __nv_bfloat16 g_vTlo[(size_t)BATCH * EMBED * SEQ];
__device__ float         g_scores[(size_t)BATCH * SEQ * SEQ];
__device__ __nv_bfloat16 g_phi[(size_t)BATCH * SEQ * SEQ];
__device__ __nv_bfloat16 g_plo[(size_t)BATCH * SEQ * SEQ];

// ---------------------------------------------------------------------------
// helpers
// ---------------------------------------------------------------------------
__device__ __forceinline__ uint32_t smem_to_u32(const void* smem_ptr) {
    uint32_t addr;
    asm("{ .reg .u64 tmp; cvta.to.shared.u64 tmp, %1; cvt.u32.u64 %0, tmp; }"
        : "=r"(addr) : "l"(smem_ptr));
    return addr;
}

// packed bf16x2 convert: low half = a, high half = b
__device__ __forceinline__ uint32_t cvt_bf16x2(float a, float b) {
    uint32_t d;
    asm("cvt.rn.bf16x2.f32 %0, %1, %2;" : "=r"(d) : "f"(b), "f"(a));
    return d;
}

__device__ __forceinline__ void ldmx4(uint32_t* r, uint32_t addr) {
    asm volatile("ldmatrix.sync.aligned.m8n8.x4.shared.b16 {%0,%1,%2,%3}, [%4];"
                 : "=r"(r[0]), "=r"(r[1]), "=r"(r[2]), "=r"(r[3]) : "r"(addr));
}

__device__ __forceinline__ void mma_bf16(float* d, const uint32_t* a,
                                         uint32_t b0, uint32_t b1) {
    asm volatile(
        "mma.sync.aligned.m16n8k16.row.col.f32.bf16.bf16.f32 "
        "{%0,%1,%2,%3}, {%4,%5,%6,%7}, {%8,%9}, {%0,%1,%2,%3};"
        : "+f"(d[0]), "+f"(d[1]), "+f"(d[2]), "+f"(d[3])
        : "r"(a[0]), "r"(a[1]), "r"(a[2]), "r"(a[3]), "r"(b0), "r"(b1));
}

#define CP16(dst, src) \
    asm volatile("{ .reg .u64 g; cvta.to.global.u64 g, %1; " \
                 "cp.async.cg.shared.global [%0], [g], 16; }" \
                 :: "r"(dst), "l"(src) : "memory")
#define CP_COMMIT() asm volatile("cp.async.commit_group;" ::: "memory")
#define CP_WAIT1()  asm volatile("cp.async.wait_group 1;" ::: "memory")

// ---------------------------------------------------------------------------
// NT GEMM (bf16x3): C[m,n] = alpha * sum_k A[m,k]*B[n,k]
// A,B given as hi/lo bf16 pairs, both K-major. CTA 128x128, 256 thr, KC=32.
// smem tile per matrix: 128 rows x 32 bf16, 64B pitch, XOR swizzle
//   unit(row,ku) = (ku ^ (row>>1)) & 3;  conflict-free for ldmatrix + cp.async
// 3-stage cp.async pipeline; one __syncthreads per chunk.
// MMA schedule keeps >=4 independent MMAs between writes to the same
// accumulator (HMMA RAW latency cover).
// ---------------------------------------------------------------------------
#define KC       32
#define MTILE_B  8192                 // 128 * 64B
#define STAGE_B  (4 * MTILE_B)        // Ahi|Alo|Bhi|Blo = 32 KB
#define NSTAGE   3
#define GEMM_SMEM (NSTAGE * STAGE_B + 128)

__device__ __forceinline__ uint32_t swz(uint32_t row, uint32_t ku) {
    return row * 64 + (((ku ^ (row >> 1)) & 3u) << 4);
}

__device__ __forceinline__ void cp_pair(const __nv_bfloat16* __restrict__ hi,
                                        const __nv_bfloat16* __restrict__ lo,
                                        int ld, int r0, int k0,
                                        uint32_t dst, int tid) {
#pragma unroll
    for (int i = 0; i < 2; i++) {
        const int idx = tid + i * 256;          // 0..511
        const uint32_t row = (uint32_t)idx >> 2;
        const uint32_t ku  = (uint32_t)idx & 3u;
        const size_t off = (size_t)(r0 + (int)row) * ld + k0 + (int)(ku * 8);
        const uint32_t d = dst + swz(row, ku);
        CP16(d,            (const void*)(hi + off));
        CP16(d + MTILE_B,  (const void*)(lo + off));
    }
}

__device__ __forceinline__ void compute_chunk(uint32_t st, int lane, int wm, int wn,
                                              float acc[4][4][4]) {
    const int r15 = lane & 15;
    const int kuh = lane >> 4;                  // 0/1: +8 k for hi half-warp
#pragma unroll
    for (int kk = 0; kk < 2; kk++) {
        const uint32_t ku = (uint32_t)(kk * 2 + kuh);
        uint32_t bh[2][4], bl[2][4];
#pragma unroll
        for (int n2 = 0; n2 < 2; n2++) {
            const uint32_t bd = st + 2 * MTILE_B + swz((uint32_t)(wn + n2 * 16 + r15), ku);
            ldmx4(bh[n2], bd);
            ldmx4(bl[n2], bd + MTILE_B);
        }
#pragma unroll
        for (int mt = 0; mt < 4; mt++) {
            const uint32_t ad = st + swz((uint32_t)(wm + mt * 16 + r15), ku);
            uint32_t ah[4], al[4];
            ldmx4(ah, ad);
            ldmx4(al, ad + MTILE_B);
            // Three passes over nt: same accumulator touched every 4 MMAs,
            // never back-to-back (covers HMMA RAW latency).
#pragma unroll
            for (int nt = 0; nt < 4; nt++) {
                const int n2 = nt >> 1, s = nt & 1;
                mma_bf16(acc[mt][nt], ah, bh[n2][s], bh[n2][2 + s]);
            }
#pragma unroll
            for (int nt = 0; nt < 4; nt++) {
                const int n2 = nt >> 1, s = nt & 1;
                mma_bf16(acc[mt][nt], ah, bl[n2][s], bl[n2][2 + s]);
            }
#pragma unroll
            for (int nt = 0; nt < 4; nt++) {
                const int n2 = nt >> 1, s = nt & 1;
                mma_bf16(acc[mt][nt], al, bh[n2][s], bh[n2][2 + s]);
            }
        }
    }
}

// mode 0: write C fp32.  mode 1: write Chi/Clo bf16 hi/lo pairs.
__global__ __launch_bounds__(256, 2)
void gemm_nt(const __nv_bfloat16* __restrict__ Ahi, const __nv_bfloat16* __restrict__ Alo,
             const __nv_bfloat16* __restrict__ Bhi, const __nv_bfloat16* __restrict__ Blo,
             float* __restrict__ C, __nv_bfloat16* __restrict__ Chi,
             __nv_bfloat16* __restrict__ Clo,
             int K, int lda, int ldb, int ldc,
             long long sA, long long sB, long long sC, float alpha, int mode)
{
    extern __shared__ char smem_raw[];
    const uint32_t smem = (smem_to_u32(smem_raw) + 127u) & ~127u;

    const int tid  = threadIdx.x;
    const int lane = tid & 31;
    const int w    = tid >> 5;
    const int wm   = (w & 1) * 64;
    const int wn   = (w >> 1) * 32;

    const int bz = blockIdx.z;
    Ahi += (size_t)bz * sA;  Alo += (size_t)bz * sA;
    Bhi += (size_t)bz * sB;  Blo += (size_t)bz * sB;
    const size_t cofs = (size_t)bz * sC;
    const int row0 = blockIdx.y * 128;
    const int col0 = blockIdx.x * 128;

    float acc[4][4][4];
#pragma unroll
    for (int i = 0; i < 4; i++)
#pragma unroll
        for (int j = 0; j < 4; j++)
#pragma unroll
            for (int q = 0; q < 4; q++) acc[i][j][q] = 0.0f;

    // prologue: chunk 0 -> stage 0, chunk 1 -> stage 1
    cp_pair(Ahi, Alo, lda, row0, 0, smem, tid);
    cp_pair(Bhi, Blo, ldb, col0, 0, smem + 2 * MTILE_B, tid);
    CP_COMMIT();
    cp_pair(Ahi, Alo, lda, row0, KC, smem + STAGE_B, tid);
    cp_pair(Bhi, Blo, ldb, col0, KC, smem + STAGE_B + 2 * MTILE_B, tid);
    CP_COMMIT();

    const int nch = K / KC;
    int cstage = 0;   // stage of current chunk
    int pstage = 2;   // stage for prefetch (chunk c+2)
#pragma unroll 1
    for (int c = 0; c < nch; c++) {
        CP_WAIT1();                // chunk c resident
        __syncthreads();
        compute_chunk(smem + (uint32_t)cstage * STAGE_B, lane, wm, wn, acc);
        if (c + 2 < nch) {
            const int k0 = (c + 2) * KC;
            const uint32_t st = smem + (uint32_t)pstage * STAGE_B;
            cp_pair(Ahi, Alo, lda, row0, k0, st, tid);
            cp_pair(Bhi, Blo, ldb, col0, k0, st + 2 * MTILE_B, tid);
        }
        CP_COMMIT();
        cstage = (cstage == 2) ? 0 : cstage + 1;
        pstage = (pstage == 2) ? 0 : pstage + 1;
    }

    // epilogue
    const int gr = lane >> 2;
    const int tc = (lane & 3) * 2;
#pragma unroll
    for (int mt = 0; mt < 4; mt++) {
#pragma unroll
        for (int nt = 0; nt < 4; nt++) {
            const size_t r0e = (size_t)(row0 + wm + mt * 16 + gr);
            const int cc = col0 + wn + nt * 8 + tc;
            float v0 = acc[mt][nt][0] * alpha, v1 = acc[mt][nt][1] * alpha;
            float v2 = acc[mt][nt][2] * alpha, v3 = acc[mt][nt][3] * alpha;
            if (mode == 0) {
                float2 a = make_float2(v0, v1), b = make_float2(v2, v3);
                *reinterpret_cast<float2*>(&C[cofs + r0e * ldc + cc])       = a;
                *reinterpret_cast<float2*>(&C[cofs + (r0e + 8) * ldc + cc]) = b;
            } else {
                uint32_t x0 = __float_as_uint(v0), x1 = __float_as_uint(v1);
                uint32_t x2 = __float_as_uint(v2), x3 = __float_as_uint(v3);
                uint32_t h01 = __byte_perm(x0, x1, 0x7632);
                uint32_t h23 = __byte_perm(x2, x3, 0x7632);
                float l0 = v0 - __uint_as_float(x0 & 0xFFFF0000u);
                float l1 = v1 - __uint_as_float(x1 & 0xFFFF0000u);
                float l2 = v2 - __uint_as_float(x2 & 0xFFFF0000u);
                float l3 = v3 - __uint_as_float(x3 & 0xFFFF0000u);
                *reinterpret_cast<uint32_t*>(&Chi[cofs + r0e * ldc + cc])       = h01;
                *reinterpret_cast<uint32_t*>(&Chi[cofs + (r0e + 8) * ldc + cc]) = h23;
                *reinterpret_cast<uint32_t*>(&Clo[cofs + r0e * ldc + cc])       = cvt_bf16x2(l0, l1);
                *reinterpret_cast<uint32_t*>(&Clo[cofs + (r0e + 8) * ldc + cc]) = cvt_bf16x2(l2, l3);
            }
        }
    }
}

// ---------------------------------------------------------------------------
// elementwise fp32 -> bf16 hi/lo
// ---------------------------------------------------------------------------
__global__ __launch_bounds__(256)
void convert_hilo(const float* __restrict__ in, __nv_bfloat16* __restrict__ hi,
                  __nv_bfloat16* __restrict__ lo)
{
    const size_t i4 = ((size_t)blockIdx.x * 256 + threadIdx.x) * 4;
    float4 v = *reinterpret_cast<const float4*>(in + i4);
    uint32_t x0 = __float_as_uint(v.x), x1 = __float_as_uint(v.y);
    uint32_t x2 = __float_as_uint(v.z), x3 = __float_as_uint(v.w);
    uint2 h;
    h.x = __byte_perm(x0, x1, 0x7632);
    h.y = __byte_perm(x2, x3, 0x7632);
    float l0 = v.x - __uint_as_float(x0 & 0xFFFF0000u);
    float l1 = v.y - __uint_as_float(x1 & 0xFFFF0000u);
    float l2 = v.z - __uint_as_float(x2 & 0xFFFF0000u);
    float l3 = v.w - __uint_as_float(x3 & 0xFFFF0000u);
    uint2 l;
    l.x = cvt_bf16x2(l0, l1);
    l.y = cvt_bf16x2(l2, l3);
    *reinterpret_cast<uint2*>(hi + i4) = h;
    *reinterpret_cast<uint2*>(lo + i4) = l;
}

// ---------------------------------------------------------------------------
// transpose + convert: W [E, 3E] f32 -> Wt hi/lo [3E, E] bf16
// ---------------------------------------------------------------------------
__global__ __launch_bounds__(256)
void transpose_convert_w(const float* __restrict__ in,
                         __nv_bfloat16* __restrict__ ohi,
                         __nv_bfloat16* __restrict__ olo)
{
    __shared__ float t[32][33];
    const int c0 = blockIdx.x * 32;   // over 3E
    const int r0 = blockIdx.y * 32;   // over E
    const int tx = threadIdx.x & 31;
    const int ty = threadIdx.x >> 5;  // 0..7
#pragma unroll
    for (int j = 0; j < 4; j++)
        t[ty + j * 8][tx] = in[(size_t)(r0 + ty + j * 8) * THREE_E + c0 + tx];
    __syncthreads();
#pragma unroll
    for (int j = 0; j < 4; j++) {
        const float v = t[tx][ty + j * 8];
        const uint32_t xb = __float_as_uint(v);
        const size_t o = (size_t)(c0 + ty + j * 8) * EMBED + r0 + tx;
        *reinterpret_cast<unsigned short*>(&ohi[o]) = (unsigned short)(xb >> 16);
        olo[o] = __float2bfloat16(v - __uint_as_float(xb & 0xFFFF0000u));
    }
}

// ---------------------------------------------------------------------------
// transpose V part of qkv (hi/lo bf16) -> vT [b][e][s]
// ---------------------------------------------------------------------------
__global__ __launch_bounds__(256)
void transpose_v(const __nv_bfloat16* __restrict__ qh,
                 const __nv_bfloat16* __restrict__ ql,
                 __nv_bfloat16* __restrict__ vh, __nv_bfloat16* __restrict__ vl)
{
    __shared__ unsigned short th[32][34];
    __shared__ unsigned short tl[32][34];
    const int b  = blockIdx.z;
    const int s0 = blockIdx.x * 32;
    const int e0 = blockIdx.y * 32;
    const int tx = threadIdx.x & 31;
    const int ty = threadIdx.x >> 5;
#pragma unroll
    for (int j = 0; j < 4; j++) {
        const size_t o = (size_t)(b * SEQ + s0 + ty + j * 8) * THREE_E + 2 * EMBED + e0 + tx;
        th[ty + j * 8][tx] = *reinterpret_cast<const unsigned short*>(&qh[o]);
        tl[ty + j * 8][tx] = *reinterpret_cast<const unsigned short*>(&ql[o]);
    }
    __syncthreads();
#pragma unroll
    for (int j = 0; j < 4; j++) {
        const size_t o = (size_t)b * EMBED * SEQ + (size_t)(e0 + ty + j * 8) * SEQ + s0 + tx;
        *reinterpret_cast<unsigned short*>(&vh[o]) = th[tx][ty + j * 8];
        *reinterpret_cast<unsigned short*>(&vl[o]) = tl[tx][ty + j * 8];
    }
}

// ---------------------------------------------------------------------------
// softmax over rows of scores; writes p as bf16 hi/lo
// ---------------------------------------------------------------------------
__global__ __launch_bounds__(256)
void softmax_rows_kernel(const float* __restrict__ S,
                         __nv_bfloat16* __restrict__ phi,
                         __nv_bfloat16* __restrict__ plo)
{
    const size_t row = blockIdx.x;
    const float* p = S + row * (size_t)SEQ;
    const int tid = threadIdx.x;

    __shared__ float red[256];

    float vals[SEQ / 256];
    float m = -INFINITY;
#pragma unroll
    for (int i = 0; i < SEQ / 256; i++) {
        vals[i] = p[tid + i * 256];
        m = fmaxf(m, vals[i]);
    }
    red[tid] = m;
    __syncthreads();
    for (int s = 128; s > 0; s >>= 1) {
        if (tid < s) red[tid] = fmaxf(red[tid], red[tid + s]);
        __syncthreads();
    }
    m = red[0];
    __syncthreads();

    float sum = 0.0f;
#pragma unroll
    for (int i = 0; i < SEQ / 256; i++) {
        vals[i] = expf(vals[i] - m);
        sum += vals[i];
    }
    red[tid] = sum;
    __syncthreads();
    for (int s = 128; s > 0; s >>= 1) {
        if (tid < s) red[tid] += red[tid + s];
        __syncthreads();
    }
    const float inv = 1.0f / red[0];

#pragma unroll
    for (int i = 0; i < SEQ / 256; i++) {
        const float v = vals[i] * inv;
        const uint32_t xb = __float_as_uint(v);
        const size_t o = row * (size_t)SEQ + tid + i * 256;
        *reinterpret_cast<unsigned short*>(&phi[o]) = (unsigned short)(xb >> 16);
        plo[o] = __float2bfloat16(v - __uint_as_float(xb & 0xFFFF0000u));
    }
}

// ---------------------------------------------------------------------------
extern "C" void kernel_launch(void* const* d_in, const int* in_sizes, int n_in,
                              void* d_out, int out_size)
{
    const float* X = (const float*)d_in[0];   // [B*S, E]
    const float* W = (const float*)d_in[1];   // [E, 3E]
    float* out = (float*)d_out;               // [B*S, E]

    __nv_bfloat16 *Xhi, *Xlo, *Wthi, *Wtlo, *qkvhi, *qkvlo, *vThi, *vTlo, *phi, *plo;
    float* scores;
    cudaGetSymbolAddress((void**)&Xhi, g_Xhi);
    cudaGetSymbolAddress((void**)&Xlo, g_Xlo);
    cudaGetSymbolAddress((void**)&Wthi, g_Wthi);
    cudaGetSymbolAddress((void**)&Wtlo, g_Wtlo);
    cudaGetSymbolAddress((void**)&qkvhi, g_qkvhi);
    cudaGetSymbolAddress((void**)&qkvlo, g_qkvlo);
    cudaGetSymbolAddress((void**)&vThi, g_vThi);
    cudaGetSymbolAddress((void**)&vTlo, g_vTlo);
    cudaGetSymbolAddress((void**)&scores, g_scores);
    cudaGetSymbolAddress((void**)&phi, g_phi);
    cudaGetSymbolAddress((void**)&plo, g_plo);

    cudaFuncSetAttribute(gemm_nt, cudaFuncAttributeMaxDynamicSharedMemorySize, GEMM_SMEM);

    const float scale = 1.0f / 32.0f;  // 1/sqrt(1024)

    // 0a) X -> bf16 hi/lo
    convert_hilo<<<(size_t)BS * EMBED / 1024, 256>>>(X, Xhi, Xlo);
    // 0b) W -> Wt bf16 hi/lo (transposed)
    transpose_convert_w<<<dim3(THREE_E / 32, EMBED / 32), 256>>>(W, Wthi, Wtlo);

    // 1) QKV = X @ W : NT with Wt.  M=8192, N=3072, K=1024 -> qkv hi/lo
    gemm_nt<<<dim3(THREE_E / 128, BS / 128, 1), 256, GEMM_SMEM>>>(
        Xhi, Xlo, Wthi, Wtlo, nullptr, qkvhi, qkvlo,
        EMBED, EMBED, EMBED, THREE_E, 0LL, 0LL, 0LL, 1.0f, 1);

    // 1b) V part -> vT hi/lo
    transpose_v<<<dim3(SEQ / 32, EMBED / 32, BATCH), 256>>>(qkvhi, qkvlo, vThi, vTlo);

    // 2) scores = scale * Q @ K^T : NT.  M=N=2048, K=1024, batched
    gemm_nt<<<dim3(SEQ / 128, SEQ / 128, BATCH), 256, GEMM_SMEM>>>(
        qkvhi, qkvlo, qkvhi + EMBED, qkvlo + EMBED, scores, nullptr, nullptr,
        EMBED, THREE_E, THREE_E, SEQ,
        (long long)SEQ * THREE_E, (long long)SEQ * THREE_E,
        (long long)SEQ * SEQ, scale, 0);

    // 3) softmax -> p hi/lo
    softmax_rows_kernel<<<BS, 256>>>(scores, phi, plo);

    // 4) out = P @ V : NT with vT.  M=2048, N=1024, K=2048, batched
    gemm_nt<<<dim3(EMBED / 128, SEQ / 128, BATCH), 256, GEMM_SMEM>>>(
        phi, plo, vThi, vTlo, out, nullptr, nullptr,
        SEQ, SEQ, SEQ, EMBED,
        (long long)SEQ * SEQ, (long long)EMBED * SEQ,
        (long long)SEQ * EMBED, 1.0f, 0);
}

// round 7
// speedup vs baseline: 4.1258x; 1.4209x over previous
#include <cuda_runtime.h>
#include <cuda_fp16.h>
#include <cstdint>
#include <math.h>

// Problem shape (fixed):
//   hidden_states [4, 2048, 1024] f32, W_qkv [1024, 3072] f32 -> out [4, 2048, 1024] f32
#define BATCH   4
#define SEQ     2048
#define EMBED   1024
#define THREE_E 3072
#define BS      (BATCH * SEQ)

// ---------------------------------------------------------------------------
// Scratch (device globals; allocation anywhere is forbidden)
// fp16 two-term scheme: A-side operands split hi+lo (exact), B-side hi only.
// ---------------------------------------------------------------------------
__device__ __half g_Xhi[(size_t)BS * EMBED];
__device__ __half g_Xlo[(size_t)BS * EMBED];
__device__ __half g_Wthi[(size_t)THREE_E * EMBED];     // W transposed [3E, E], hi only
__device__ __half g_qkvhi[(size_t)BS * THREE_E];
__device__ __half g_qkvlo[(size_t)BS * THREE_E];
__device__ __half g_vThi[(size_t)BATCH * EMBED * SEQ]; // V^T [b][e][s], hi only
__device__ float  g_scores[(size_t)BATCH * SEQ * SEQ];
__device__ __half g_phi[(size_t)BATCH * SEQ * SEQ];
__device__ __half g_plo[(size_t)BATCH * SEQ * SEQ];

// ---------------------------------------------------------------------------
// helpers
// ---------------------------------------------------------------------------
__device__ __forceinline__ uint32_t smem_to_u32(const void* smem_ptr) {
    uint32_t addr;
    asm("{ .reg .u64 tmp; cvta.to.shared.u64 tmp, %1; cvt.u32.u64 %0, tmp; }"
        : "=r"(addr) : "l"(smem_ptr));
    return addr;
}

__device__ __forceinline__ void ldmx4(uint32_t* r, uint32_t addr) {
    asm volatile("ldmatrix.sync.aligned.m8n8.x4.shared.b16 {%0,%1,%2,%3}, [%4];"
                 : "=r"(r[0]), "=r"(r[1]), "=r"(r[2]), "=r"(r[3]) : "r"(addr));
}

__device__ __forceinline__ void mma_f16(float* d, const uint32_t* a,
                                        uint32_t b0, uint32_t b1) {
    asm volatile(
        "mma.sync.aligned.m16n8k16.row.col.f32.f16.f16.f32 "
        "{%0,%1,%2,%3}, {%4,%5,%6,%7}, {%8,%9}, {%0,%1,%2,%3};"
        : "+f"(d[0]), "+f"(d[1]), "+f"(d[2]), "+f"(d[3])
        : "r"(a[0]), "r"(a[1]), "r"(a[2]), "r"(a[3]), "r"(b0), "r"(b1));
}

#define CP16(dst, src) \
    asm volatile("{ .reg .u64 g; cvta.to.global.u64 g, %1; " \
                 "cp.async.cg.shared.global [%0], [g], 16; }" \
                 :: "r"(dst), "l"(src) : "memory")
#define CP_COMMIT() asm volatile("cp.async.commit_group;" ::: "memory")
#define CP_WAIT1()  asm volatile("cp.async.wait_group 1;" ::: "memory")

// fp16 hi/lo split of one float (exact two-term representation)
__device__ __forceinline__ void split_f16(float v, __half& h, __half& l) {
    h = __float2half_rn(v);
    l = __float2half_rn(v - __half2float(h));
}

// ---------------------------------------------------------------------------
// NT GEMM (fp16 two-term): C[m,n] = alpha * sum_k A[m,k]*B[n,k]
//   C = Ahi*Bhi + Alo*Bhi   (A = Ahi+Alo exact; error = A*(B-Bhi) ~ 2^-12)
// CTA 128x128, 256 thr, KC=32. smem per matrix: 128 rows x 32 f16, 64B pitch,
// XOR swizzle unit(row,ku) = (ku ^ (row>>1)) & 3. 3-stage cp.async pipeline.
// ---------------------------------------------------------------------------
#define KC       32
#define MTILE_B  8192                 // 128 * 64B
#define STAGE_B  (3 * MTILE_B)        // Ahi|Alo|Bhi = 24 KB
#define NSTAGE   3
#define GEMM_SMEM (NSTAGE * STAGE_B + 128)

__device__ __forceinline__ uint32_t swz(uint32_t row, uint32_t ku) {
    return row * 64 + (((ku ^ (row >> 1)) & 3u) << 4);
}

// A: hi+lo pair into [dst, dst+MTILE_B]
__device__ __forceinline__ void cp_a(const __half* __restrict__ hi,
                                     const __half* __restrict__ lo,
                                     int ld, int r0, int k0,
                                     uint32_t dst, int tid) {
#pragma unroll
    for (int i = 0; i < 2; i++) {
        const int idx = tid + i * 256;          // 0..511
        const uint32_t row = (uint32_t)idx >> 2;
        const uint32_t ku  = (uint32_t)idx & 3u;
        const size_t off = (size_t)(r0 + (int)row) * ld + k0 + (int)(ku * 8);
        const uint32_t d = dst + swz(row, ku);
        CP16(d,           (const void*)(hi + off));
        CP16(d + MTILE_B, (const void*)(lo + off));
    }
}
// B: hi only into dst
__device__ __forceinline__ void cp_b(const __half* __restrict__ hi,
                                     int ld, int r0, int k0,
                                     uint32_t dst, int tid) {
#pragma unroll
    for (int i = 0; i < 2; i++) {
        const int idx = tid + i * 256;
        const uint32_t row = (uint32_t)idx >> 2;
        const uint32_t ku  = (uint32_t)idx & 3u;
        const size_t off = (size_t)(r0 + (int)row) * ld + k0 + (int)(ku * 8);
        CP16(dst + swz(row, ku), (const void*)(hi + off));
    }
}

__device__ __forceinline__ void compute_chunk(uint32_t st, int lane, int wm, int wn,
                                              float acc[4][4][4]) {
    const int r15 = lane & 15;
    const int kuh = lane >> 4;                  // 0/1: +8 k for hi half-warp
#pragma unroll
    for (int kk = 0; kk < 2; kk++) {
        const uint32_t ku = (uint32_t)(kk * 2 + kuh);
        uint32_t bh[2][4];
#pragma unroll
        for (int n2 = 0; n2 < 2; n2++) {
            ldmx4(bh[n2], st + 2 * MTILE_B + swz((uint32_t)(wn + n2 * 16 + r15), ku));
        }
#pragma unroll
        for (int mt = 0; mt < 4; mt++) {
            const uint32_t ad = st + swz((uint32_t)(wm + mt * 16 + r15), ku);
            uint32_t ah[4], al[4];
            ldmx4(ah, ad);
            ldmx4(al, ad + MTILE_B);
#pragma unroll
            for (int nt = 0; nt < 4; nt++) {
                const int n2 = nt >> 1, s = nt & 1;
                mma_f16(acc[mt][nt], ah, bh[n2][s], bh[n2][2 + s]);
            }
#pragma unroll
            for (int nt = 0; nt < 4; nt++) {
                const int n2 = nt >> 1, s = nt & 1;
                mma_f16(acc[mt][nt], al, bh[n2][s], bh[n2][2 + s]);
            }
        }
    }
}

// mode 0: write C fp32.  mode 1: write Chi/Clo fp16 hi/lo pairs.
__global__ __launch_bounds__(256, 2)
void gemm_nt(const __half* __restrict__ Ahi, const __half* __restrict__ Alo,
             const __half* __restrict__ Bhi,
             float* __restrict__ C, __half* __restrict__ Chi, __half* __restrict__ Clo,
             int K, int lda, int ldb, int ldc,
             long long sA, long long sB, long long sC, float alpha, int mode)
{
    extern __shared__ char smem_raw[];
    const uint32_t smem = (smem_to_u32(smem_raw) + 127u) & ~127u;

    const int tid  = threadIdx.x;
    const int lane = tid & 31;
    const int w    = tid >> 5;
    const int wm   = (w & 1) * 64;
    const int wn   = (w >> 1) * 32;

    const int bz = blockIdx.z;
    Ahi += (size_t)bz * sA;  Alo += (size_t)bz * sA;
    Bhi += (size_t)bz * sB;
    const size_t cofs = (size_t)bz * sC;
    const int row0 = blockIdx.y * 128;
    const int col0 = blockIdx.x * 128;

    float acc[4][4][4];
#pragma unroll
    for (int i = 0; i < 4; i++)
#pragma unroll
        for (int j = 0; j < 4; j++)
#pragma unroll
            for (int q = 0; q < 4; q++) acc[i][j][q] = 0.0f;

    // prologue: chunk 0 -> stage 0, chunk 1 -> stage 1
    cp_a(Ahi, Alo, lda, row0, 0, smem, tid);
    cp_b(Bhi, ldb, col0, 0, smem + 2 * MTILE_B, tid);
    CP_COMMIT();
    cp_a(Ahi, Alo, lda, row0, KC, smem + STAGE_B, tid);
    cp_b(Bhi, ldb, col0, KC, smem + STAGE_B + 2 * MTILE_B, tid);
    CP_COMMIT();

    const int nch = K / KC;
    int cstage = 0;
    int pstage = 2;
#pragma unroll 1
    for (int c = 0; c < nch; c++) {
        CP_WAIT1();
        __syncthreads();
        compute_chunk(smem + (uint32_t)cstage * STAGE_B, lane, wm, wn, acc);
        if (c + 2 < nch) {
            const int k0 = (c + 2) * KC;
            const uint32_t st = smem + (uint32_t)pstage * STAGE_B;
            cp_a(Ahi, Alo, lda, row0, k0, st, tid);
            cp_b(Bhi, ldb, col0, k0, st + 2 * MTILE_B, tid);
        }
        CP_COMMIT();
        cstage = (cstage == 2) ? 0 : cstage + 1;
        pstage = (pstage == 2) ? 0 : pstage + 1;
    }

    // epilogue
    const int gr = lane >> 2;
    const int tc = (lane & 3) * 2;
#pragma unroll
    for (int mt = 0; mt < 4; mt++) {
#pragma unroll
        for (int nt = 0; nt < 4; nt++) {
            const size_t r0e = (size_t)(row0 + wm + mt * 16 + gr);
            const int cc = col0 + wn + nt * 8 + tc;
            float v0 = acc[mt][nt][0] * alpha, v1 = acc[mt][nt][1] * alpha;
            float v2 = acc[mt][nt][2] * alpha, v3 = acc[mt][nt][3] * alpha;
            if (mode == 0) {
                float2 a = make_float2(v0, v1), b = make_float2(v2, v3);
                *reinterpret_cast<float2*>(&C[cofs + r0e * ldc + cc])       = a;
                *reinterpret_cast<float2*>(&C[cofs + (r0e + 8) * ldc + cc]) = b;
            } else {
                __half h0, h1, h2, h3, l0, l1, l2, l3;
                split_f16(v0, h0, l0); split_f16(v1, h1, l1);
                split_f16(v2, h2, l2); split_f16(v3, h3, l3);
                __half2 H01 = __halves2half2(h0, h1), H23 = __halves2half2(h2, h3);
                __half2 L01 = __halves2half2(l0, l1), L23 = __halves2half2(l2, l3);
                *reinterpret_cast<__half2*>(&Chi[cofs + r0e * ldc + cc])       = H01;
                *reinterpret_cast<__half2*>(&Chi[cofs + (r0e + 8) * ldc + cc]) = H23;
                *reinterpret_cast<__half2*>(&Clo[cofs + r0e * ldc + cc])       = L01;
                *reinterpret_cast<__half2*>(&Clo[cofs + (r0e + 8) * ldc + cc]) = L23;
            }
        }
    }
}

// ---------------------------------------------------------------------------
// elementwise fp32 -> fp16 hi/lo
// ---------------------------------------------------------------------------
__global__ __launch_bounds__(256)
void convert_hilo(const float* __restrict__ in, __half* __restrict__ hi,
                  __half* __restrict__ lo)
{
    const size_t i4 = ((size_t)blockIdx.x * 256 + threadIdx.x) * 4;
    float4 v = *reinterpret_cast<const float4*>(in + i4);
    __half h0, h1, h2, h3, l0, l1, l2, l3;
    split_f16(v.x, h0, l0); split_f16(v.y, h1, l1);
    split_f16(v.z, h2, l2); split_f16(v.w, h3, l3);
    __half2 H01 = __halves2half2(h0, h1), H23 = __halves2half2(h2, h3);
    __half2 L01 = __halves2half2(l0, l1), L23 = __halves2half2(l2, l3);
    *reinterpret_cast<__half2*>(hi + i4)     = H01;
    *reinterpret_cast<__half2*>(hi + i4 + 2) = H23;
    *reinterpret_cast<__half2*>(lo + i4)     = L01;
    *reinterpret_cast<__half2*>(lo + i4 + 2) = L23;
}

// ---------------------------------------------------------------------------
// transpose + convert: W [E, 3E] f32 -> Wt hi [3E, E] fp16 (B-side, hi only)
// ---------------------------------------------------------------------------
__global__ __launch_bounds__(256)
void transpose_convert_w(const float* __restrict__ in, __half* __restrict__ ohi)
{
    __shared__ float t[32][33];
    const int c0 = blockIdx.x * 32;   // over 3E
    const int r0 = blockIdx.y * 32;   // over E
    const int tx = threadIdx.x & 31;
    const int ty = threadIdx.x >> 5;  // 0..7
#pragma unroll
    for (int j = 0; j < 4; j++)
        t[ty + j * 8][tx] = in[(size_t)(r0 + ty + j * 8) * THREE_E + c0 + tx];
    __syncthreads();
#pragma unroll
    for (int j = 0; j < 4; j++) {
        const float v = t[tx][ty + j * 8];
        ohi[(size_t)(c0 + ty + j * 8) * EMBED + r0 + tx] = __float2half_rn(v);
    }
}

// ---------------------------------------------------------------------------
// transpose V part of qkv (hi fp16) -> vT [b][e][s] (hi only)
// ---------------------------------------------------------------------------
__global__ __launch_bounds__(256)
void transpose_v(const __half* __restrict__ qh, __half* __restrict__ vh)
{
    __shared__ unsigned short th[32][34];
    const int b  = blockIdx.z;
    const int s0 = blockIdx.x * 32;
    const int e0 = blockIdx.y * 32;
    const int tx = threadIdx.x & 31;
    const int ty = threadIdx.x >> 5;
#pragma unroll
    for (int j = 0; j < 4; j++) {
        const size_t o = (size_t)(b * SEQ + s0 + ty + j * 8) * THREE_E + 2 * EMBED + e0 + tx;
        th[ty + j * 8][tx] = *reinterpret_cast<const unsigned short*>(&qh[o]);
    }
    __syncthreads();
#pragma unroll
    for (int j = 0; j < 4; j++) {
        const size_t o = (size_t)b * EMBED * SEQ + (size_t)(e0 + ty + j * 8) * SEQ + s0 + tx;
        *reinterpret_cast<unsigned short*>(&vh[o]) = th[tx][ty + j * 8];
    }
}

// NOTE: V used as B-side only needs hi; but V itself came from GEMM1 with
// fp16 rounding of B=W — errors stay ~1e-4 level.

// ---------------------------------------------------------------------------
// softmax over rows of scores; writes p as fp16 hi/lo
// ---------------------------------------------------------------------------
__global__ __launch_bounds__(256)
void softmax_rows_kernel(const float* __restrict__ S,
                         __half* __restrict__ phi, __half* __restrict__ plo)
{
    const size_t row = blockIdx.x;
    const float* p = S + row * (size_t)SEQ;
    const int tid = threadIdx.x;

    __shared__ float red[256];

    float vals[SEQ / 256];
    float m = -INFINITY;
#pragma unroll
    for (int i = 0; i < SEQ / 256; i++) {
        vals[i] = p[tid + i * 256];
        m = fmaxf(m, vals[i]);
    }
    red[tid] = m;
    __syncthreads();
    for (int s = 128; s > 0; s >>= 1) {
        if (tid < s) red[tid] = fmaxf(red[tid], red[tid + s]);
        __syncthreads();
    }
    m = red[0];
    __syncthreads();

    float sum = 0.0f;
#pragma unroll
    for (int i = 0; i < SEQ / 256; i++) {
        vals[i] = expf(vals[i] - m);
        sum += vals[i];
    }
    red[tid] = sum;
    __syncthreads();
    for (int s = 128; s > 0; s >>= 1) {
        if (tid < s) red[tid] += red[tid + s];
        __syncthreads();
    }
    const float inv = 1.0f / red[0];

#pragma unroll
    for (int i = 0; i < SEQ / 256; i++) {
        const float v = vals[i] * inv;
        __half h, l;
        split_f16(v, h, l);
        const size_t o = row * (size_t)SEQ + tid + i * 256;
        phi[o] = h;
        plo[o] = l;
    }
}

// ---------------------------------------------------------------------------
extern "C" void kernel_launch(void* const* d_in, const int* in_sizes, int n_in,
                              void* d_out, int out_size)
{
    const float* X = (const float*)d_in[0];   // [B*S, E]
    const float* W = (const float*)d_in[1];   // [E, 3E]
    float* out = (float*)d_out;               // [B*S, E]

    __half *Xhi, *Xlo, *Wthi, *qkvhi, *qkvlo, *vThi, *phi, *plo;
    float* scores;
    cudaGetSymbolAddress((void**)&Xhi, g_Xhi);
    cudaGetSymbolAddress((void**)&Xlo, g_Xlo);
    cudaGetSymbolAddress((void**)&Wthi, g_Wthi);
    cudaGetSymbolAddress((void**)&qkvhi, g_qkvhi);
    cudaGetSymbolAddress((void**)&qkvlo, g_qkvlo);
    cudaGetSymbolAddress((void**)&vThi, g_vThi);
    cudaGetSymbolAddress((void**)&scores, g_scores);
    cudaGetSymbolAddress((void**)&phi, g_phi);
    cudaGetSymbolAddress((void**)&plo, g_plo);

    cudaFuncSetAttribute(gemm_nt, cudaFuncAttributeMaxDynamicSharedMemorySize, GEMM_SMEM);

    const float scale = 1.0f / 32.0f;  // 1/sqrt(1024)

    // 0a) X -> fp16 hi/lo
    convert_hilo<<<(size_t)BS * EMBED / 1024, 256>>>(X, Xhi, Xlo);
    // 0b) W -> Wt fp16 hi (transposed)
    transpose_convert_w<<<dim3(THREE_E / 32, EMBED / 32), 256>>>(W, Wthi);

    // 1) QKV = X @ W : NT with Wt.  M=8192, N=3072, K=1024 -> qkv hi/lo
    gemm_nt<<<dim3(THREE_E / 128, BS / 128, 1), 256, GEMM_SMEM>>>(
        Xhi, Xlo, Wthi, nullptr, qkvhi, qkvlo,
        EMBED, EMBED, EMBED, THREE_E, 0LL, 0LL, 0LL, 1.0f, 1);

    // 1b) V part -> vT hi
    transpose_v<<<dim3(SEQ / 32, EMBED / 32, BATCH), 256>>>(qkvhi, vThi);

    // 2) scores = scale * Q @ K^T : NT.  M=N=2048, K=1024, batched
    gemm_nt<<<dim3(SEQ / 128, SEQ / 128, BATCH), 256, GEMM_SMEM>>>(
        qkvhi, qkvlo, qkvhi + EMBED, scores, nullptr, nullptr,
        EMBED, THREE_E, THREE_E, SEQ,
        (long long)SEQ * THREE_E, (long long)SEQ * THREE_E,
        (long long)SEQ * SEQ, scale, 0);

    // 3) softmax -> p hi/lo
    softmax_rows_kernel<<<BS, 256>>>(scores, phi, plo);

    // 4) out = P @ V : NT with vT.  M=2048, N=1024, K=2048, batched
    gemm_nt<<<dim3(EMBED / 128, SEQ / 128, BATCH), 256, GEMM_SMEM>>>(
        phi, plo, vThi, out, nullptr, nullptr,
        SEQ, SEQ, SEQ, EMBED,
        (long long)SEQ * SEQ, (long long)EMBED * SEQ,
        (long long)SEQ * EMBED, 1.0f, 0);
}